// round 2
// baseline (speedup 1.0000x reference)
#include <cuda_runtime.h>
#include <math.h>

// ---------------------------------------------------------------------------
// Problem constants
// B=32, N=1024, DIM=512, HEADS=8, HEAD_DIM=64, MLP_HIDDEN=2048
// M = B*N = 32768 token rows.
// ---------------------------------------------------------------------------
#define MROWS 32768
#define DIMC  512
#define HIDC  2048

// Scratch (static device globals; allocation inside kernel_launch is banned)
__device__ float d_h  [MROWS * DIMC];   // LN output (reused for LN1 and LN2)
__device__ float d_q  [MROWS * DIMC];   // [B*H, 1024, 64]
__device__ float d_k  [MROWS * DIMC];
__device__ float d_v  [MROWS * DIMC];
__device__ float d_o  [MROWS * DIMC];   // attention output, [B, tok, 512]
__device__ float d_x1 [MROWS * DIMC];   // after first residual
__device__ float d_hid[MROWS * HIDC];   // MLP hidden

// ---------------------------------------------------------------------------
// LayerNorm: one block per row of 512, 128 threads, float4 per thread
// ---------------------------------------------------------------------------
__global__ void __launch_bounds__(128) ln_kernel(
    const float* __restrict__ x, const float* __restrict__ g,
    const float* __restrict__ b, float* __restrict__ out)
{
    int row = blockIdx.x;
    int t = threadIdx.x;
    const float4* xr = reinterpret_cast<const float4*>(x + (size_t)row * DIMC);
    float4 vv = xr[t];
    float s  = vv.x + vv.y + vv.z + vv.w;
    float sq = vv.x*vv.x + vv.y*vv.y + vv.z*vv.z + vv.w*vv.w;
    #pragma unroll
    for (int o = 16; o > 0; o >>= 1) {
        s  += __shfl_xor_sync(0xffffffffu, s,  o);
        sq += __shfl_xor_sync(0xffffffffu, sq, o);
    }
    __shared__ float ss[4], sq2[4];
    int w = t >> 5;
    if ((t & 31) == 0) { ss[w] = s; sq2[w] = sq; }
    __syncthreads();
    s  = ss[0] + ss[1] + ss[2] + ss[3];
    sq = sq2[0] + sq2[1] + sq2[2] + sq2[3];
    float mu  = s * (1.f / DIMC);
    float var = sq * (1.f / DIMC) - mu * mu;
    float inv = rsqrtf(var + 1e-5f);
    float4 gv = reinterpret_cast<const float4*>(g)[t];
    float4 bv = reinterpret_cast<const float4*>(b)[t];
    float4 ov;
    ov.x = (vv.x - mu) * inv * gv.x + bv.x;
    ov.y = (vv.y - mu) * inv * gv.y + bv.y;
    ov.z = (vv.z - mu) * inv * gv.z + bv.z;
    ov.w = (vv.w - mu) * inv * gv.w + bv.w;
    reinterpret_cast<float4*>(out + (size_t)row * DIMC)[t] = ov;
}

// ---------------------------------------------------------------------------
// SGEMM: C[M,N] = A[M,K] * B[N,K]^T  (both row-major, K contiguous)
// 128x128x16 tile, 256 threads, 8x8 microtile per thread.
// Epilogues fused via template.
// ---------------------------------------------------------------------------
enum { EPI_QKV = 0, EPI_PROJ = 1, EPI_GELU = 2, EPI_OUT = 3 };

template<int K, int EPI>
__global__ void __launch_bounds__(256) sgemm_kernel(
    const float* __restrict__ A, const float* __restrict__ B,
    float* __restrict__ out, const float* __restrict__ bias,
    const float* __restrict__ resid,
    float* __restrict__ oq, float* __restrict__ ok, float* __restrict__ ov,
    int N)
{
    __shared__ float As[16][128];
    __shared__ float Bs[16][128];
    int m0 = blockIdx.y << 7, n0 = blockIdx.x << 7;
    int t = threadIdx.x;
    int lrow = t >> 2;            // 0..63
    int lk4  = (t & 3) << 2;      // 0,4,8,12
    int ty = t >> 4, tx = t & 15; // 16x16 compute grid

    float acc[8][8];
    #pragma unroll
    for (int i = 0; i < 8; i++)
        #pragma unroll
        for (int j = 0; j < 8; j++) acc[i][j] = 0.f;

    const float* Ab = A + (size_t)(m0 + lrow) * K + lk4;
    const float* Bb = B + (size_t)(n0 + lrow) * K + lk4;

    for (int k0 = 0; k0 < K; k0 += 16) {
        float4 a0 = *(const float4*)(Ab + k0);
        float4 a1 = *(const float4*)(Ab + (size_t)64 * K + k0);
        float4 b0 = *(const float4*)(Bb + k0);
        float4 b1 = *(const float4*)(Bb + (size_t)64 * K + k0);
        As[lk4+0][lrow]    = a0.x; As[lk4+1][lrow]    = a0.y;
        As[lk4+2][lrow]    = a0.z; As[lk4+3][lrow]    = a0.w;
        As[lk4+0][lrow+64] = a1.x; As[lk4+1][lrow+64] = a1.y;
        As[lk4+2][lrow+64] = a1.z; As[lk4+3][lrow+64] = a1.w;
        Bs[lk4+0][lrow]    = b0.x; Bs[lk4+1][lrow]    = b0.y;
        Bs[lk4+2][lrow]    = b0.z; Bs[lk4+3][lrow]    = b0.w;
        Bs[lk4+0][lrow+64] = b1.x; Bs[lk4+1][lrow+64] = b1.y;
        Bs[lk4+2][lrow+64] = b1.z; Bs[lk4+3][lrow+64] = b1.w;
        __syncthreads();
        #pragma unroll
        for (int kk = 0; kk < 16; kk++) {
            float a[8], b[8];
            *(float4*)&a[0] = *(float4*)&As[kk][ty*8];
            *(float4*)&a[4] = *(float4*)&As[kk][ty*8+4];
            *(float4*)&b[0] = *(float4*)&Bs[kk][tx*8];
            *(float4*)&b[4] = *(float4*)&Bs[kk][tx*8+4];
            #pragma unroll
            for (int i = 0; i < 8; i++)
                #pragma unroll
                for (int j = 0; j < 8; j++)
                    acc[i][j] += a[i] * b[j];
        }
        __syncthreads();
    }

    #pragma unroll
    for (int i = 0; i < 8; i++) {
        int m = m0 + ty * 8 + i;
        #pragma unroll
        for (int j = 0; j < 8; j++) {
            int n = n0 + tx * 8 + j;
            float c = acc[i][j];
            if (EPI == EPI_QKV) {
                // scatter into q/k/v [B*H, 1024, 64]
                int sec = n >> 9;            // 0=q,1=k,2=v
                int hh  = (n >> 6) & 7;
                int dd  = n & 63;
                int bb  = m >> 10;
                int tok = m & 1023;
                float* dst = (sec == 0) ? oq : ((sec == 1) ? ok : ov);
                dst[(((size_t)bb * 8 + hh) * 1024 + tok) * 64 + dd] = c;
            } else if (EPI == EPI_PROJ) {
                out[(size_t)m * N + n] = resid[(size_t)m * N + n] + c + bias[n];
            } else if (EPI == EPI_GELU) {
                float u = c + bias[n];
                out[(size_t)m * N + n] =
                    0.5f * u * (1.f + erff(u * 0.70710678118654752f));
            } else { // EPI_OUT
                out[(size_t)m * N + n] = resid[(size_t)m * N + n] + c + bias[n];
            }
        }
    }
}

// ---------------------------------------------------------------------------
// Fused flash attention with clipped relative-position bias.
// grid = (16 q-tiles, 256 bh), 256 threads. Tiles 64x64, d=64.
// SMEM layout (floats): qs[4096] ks[4096] vs[4096] sb[64*65] btab[225+pad]
//                       mrow[64] lrow[64] arow[64]  -> 67584 bytes
// ---------------------------------------------------------------------------
#define ATTN_SMEM_BYTES (16896 * 4)

__global__ void __launch_bounds__(256) attn_kernel(
    const float* __restrict__ q, const float* __restrict__ k,
    const float* __restrict__ v, const float* __restrict__ btab_g,
    float* __restrict__ o)
{
    extern __shared__ float sm[];
    float* qs   = sm;           // [d][row]  (d-major)
    float* ks   = sm + 4096;    // [d][col]
    float* vs   = sm + 8192;    // [row][d]
    float* sb   = sm + 12288;   // [64][65]
    float* btab = sm + 16448;   // 225
    float* mrow = sm + 16704;
    float* lrow = sm + 16768;
    float* arow = sm + 16832;

    int qt = blockIdx.x, bh = blockIdx.y;
    int hh = bh & 7;
    int t = threadIdx.x;
    int ty = t >> 4, tx = t & 15;
    int r0 = ty * 4, c0 = tx * 4;

    for (int i = t; i < 225; i += 256) btab[i] = btab_g[i * 8 + hh];

    const float* qbase = q + ((size_t)bh * 1024 + qt * 64) * 64;
    #pragma unroll
    for (int r = 0; r < 4; r++) {
        int idx = t + 256 * r;
        int row = idx >> 4;
        int d4  = (idx & 15) << 2;
        float4 qv = *(const float4*)(qbase + row * 64 + d4);
        qs[(d4+0)*64+row] = qv.x; qs[(d4+1)*64+row] = qv.y;
        qs[(d4+2)*64+row] = qv.z; qs[(d4+3)*64+row] = qv.w;
    }
    if (t < 64) { mrow[t] = -1e30f; lrow[t] = 0.f; }
    float oacc[4][4] = {};
    __syncthreads();

    for (int kt = 0; kt < 16; kt++) {
        const float* kbp = k + ((size_t)bh * 1024 + kt * 64) * 64;
        const float* vbp = v + ((size_t)bh * 1024 + kt * 64) * 64;
        #pragma unroll
        for (int r = 0; r < 4; r++) {
            int idx = t + 256 * r;
            int row = idx >> 4;
            int d4  = (idx & 15) << 2;
            float4 kv = *(const float4*)(kbp + row * 64 + d4);
            ks[(d4+0)*64+row] = kv.x; ks[(d4+1)*64+row] = kv.y;
            ks[(d4+2)*64+row] = kv.z; ks[(d4+3)*64+row] = kv.w;
            float4 vv = *(const float4*)(vbp + row * 64 + d4);
            *(float4*)&vs[row * 64 + d4] = vv;
        }
        __syncthreads();

        // s = q @ k^T  (4x4 microtile per thread)
        float s[4][4] = {};
        #pragma unroll
        for (int d = 0; d < 64; d++) {
            float4 av = *(float4*)&qs[d * 64 + r0];
            float4 bv = *(float4*)&ks[d * 64 + c0];
            float a_[4] = {av.x, av.y, av.z, av.w};
            float b_[4] = {bv.x, bv.y, bv.z, bv.w};
            #pragma unroll
            for (int i = 0; i < 4; i++)
                #pragma unroll
                for (int j = 0; j < 4; j++)
                    s[i][j] += a_[i] * b_[j];
        }
        // scale + relative-position bias -> sb
        int qi0 = qt * 64 + r0, kj0 = kt * 64 + c0;
        #pragma unroll
        for (int i = 0; i < 4; i++) {
            int qi = qi0 + i;
            int qy = qi >> 5, qx = qi & 31;
            #pragma unroll
            for (int j = 0; j < 4; j++) {
                int kj = kj0 + j;
                int dy = qy - (kj >> 5) + 31;
                int dx = qx - (kj & 31) + 31;
                int id = dy * 63 + dx;
                id = id < 224 ? id : 224;
                sb[(r0 + i) * 65 + c0 + j] = s[i][j] * 0.125f + btab[id];
            }
        }
        __syncthreads();

        // online softmax (one thread per row)
        if (t < 64) {
            float* row = &sb[t * 65];
            float mold = mrow[t];
            float tm = mold;
            #pragma unroll
            for (int j = 0; j < 64; j++) tm = fmaxf(tm, row[j]);
            float alpha = __expf(mold - tm);
            float sum = 0.f;
            #pragma unroll
            for (int j = 0; j < 64; j++) {
                float e = __expf(row[j] - tm);
                row[j] = e;
                sum += e;
            }
            lrow[t] = lrow[t] * alpha + sum;
            mrow[t] = tm;
            arow[t] = alpha;
        }
        __syncthreads();

        // rescale accumulator, then o += P @ V
        #pragma unroll
        for (int i = 0; i < 4; i++) {
            float al = arow[r0 + i];
            #pragma unroll
            for (int j = 0; j < 4; j++) oacc[i][j] *= al;
        }
        #pragma unroll
        for (int kk = 0; kk < 64; kk++) {
            float4 vv = *(float4*)&vs[kk * 64 + c0];
            float vb[4] = {vv.x, vv.y, vv.z, vv.w};
            #pragma unroll
            for (int i = 0; i < 4; i++) {
                float p = sb[(r0 + i) * 65 + kk];
                #pragma unroll
                for (int j = 0; j < 4; j++) oacc[i][j] += p * vb[j];
            }
        }
        __syncthreads();
    }

    // write o as [B, tok, h*64+d]
    int bb = bh >> 3;
    #pragma unroll
    for (int i = 0; i < 4; i++) {
        int row = r0 + i;
        float inv = 1.f / lrow[row];
        int tok = qt * 64 + row;
        float4 ov;
        ov.x = oacc[i][0] * inv; ov.y = oacc[i][1] * inv;
        ov.z = oacc[i][2] * inv; ov.w = oacc[i][3] * inv;
        *(float4*)(o + ((size_t)bb * 1024 + tok) * 512 + hh * 64 + c0) = ov;
    }
}

// ---------------------------------------------------------------------------
// Launcher
// ---------------------------------------------------------------------------
extern "C" void kernel_launch(void* const* d_in, const int* in_sizes, int n_in,
                              void* d_out, int out_size)
{
    const float* x      = (const float*)d_in[0];
    const float* qkv_w  = (const float*)d_in[1];
    const float* proj_w = (const float*)d_in[2];
    const float* proj_b = (const float*)d_in[3];
    const float* mlp_w1 = (const float*)d_in[4];
    const float* mlp_b1 = (const float*)d_in[5];
    const float* mlp_w2 = (const float*)d_in[6];
    const float* mlp_b2 = (const float*)d_in[7];
    const float* n1g    = (const float*)d_in[8];
    const float* n1b    = (const float*)d_in[9];
    const float* n2g    = (const float*)d_in[10];
    const float* n2b    = (const float*)d_in[11];
    const float* btab   = (const float*)d_in[12];
    float* out = (float*)d_out;

    float *h, *q, *k, *v, *o, *x1, *hid;
    cudaGetSymbolAddress((void**)&h,   d_h);
    cudaGetSymbolAddress((void**)&q,   d_q);
    cudaGetSymbolAddress((void**)&k,   d_k);
    cudaGetSymbolAddress((void**)&v,   d_v);
    cudaGetSymbolAddress((void**)&o,   d_o);
    cudaGetSymbolAddress((void**)&x1,  d_x1);
    cudaGetSymbolAddress((void**)&hid, d_hid);

    cudaFuncSetAttribute(attn_kernel,
        cudaFuncAttributeMaxDynamicSharedMemorySize, ATTN_SMEM_BYTES);

    // LN1
    ln_kernel<<<MROWS, 128>>>(x, n1g, n1b, h);
    // QKV gemm (+ scatter to per-head layout)
    sgemm_kernel<512, EPI_QKV><<<dim3(12, 256), 256>>>(
        h, qkv_w, nullptr, nullptr, nullptr, q, k, v, 1536);
    // fused attention
    attn_kernel<<<dim3(16, 256), 256, ATTN_SMEM_BYTES>>>(q, k, v, btab, o);
    // proj + bias + residual
    sgemm_kernel<512, EPI_PROJ><<<dim3(4, 256), 256>>>(
        o, proj_w, x1, proj_b, x, nullptr, nullptr, nullptr, 512);
    // LN2
    ln_kernel<<<MROWS, 128>>>(x1, n2g, n2b, h);
    // MLP1 + gelu
    sgemm_kernel<512, EPI_GELU><<<dim3(16, 256), 256>>>(
        h, mlp_w1, hid, mlp_b1, nullptr, nullptr, nullptr, nullptr, 2048);
    // MLP2 + bias + residual -> out
    sgemm_kernel<2048, EPI_OUT><<<dim3(4, 256), 256>>>(
        hid, mlp_w2, out, mlp_b2, x1, nullptr, nullptr, nullptr, 512);
}

// round 4
// speedup vs baseline: 1.5592x; 1.5592x over previous
#include <cuda_runtime.h>
#include <cuda_bf16.h>
#include <math.h>
#include <stdint.h>

// ---------------------------------------------------------------------------
// B=32, N=1024, DIM=512, HEADS=8, HEAD_DIM=64, MLP_HIDDEN=2048. M = 32768.
// GEMMs via mma.sync bf16 (bf16x3 split => fp32-class accuracy).
// NOTE: harness PTX target is compute_103 (no 'a') -> no tcgen05/TMA.
// ---------------------------------------------------------------------------
#define MROWS 32768
#define DIMC  512
#define HIDC  2048

// fp32 scratch
__device__ float d_q [MROWS * DIMC];
__device__ float d_k [MROWS * DIMC];
__device__ float d_v [MROWS * DIMC];
__device__ float d_o [MROWS * DIMC];
__device__ float d_x1[MROWS * DIMC];
// bf16 split activations
__device__ __nv_bfloat16 g_h_hi [MROWS * DIMC];
__device__ __nv_bfloat16 g_h_lo [MROWS * DIMC];
__device__ __nv_bfloat16 g_o_hi [MROWS * DIMC];
__device__ __nv_bfloat16 g_o_lo [MROWS * DIMC];
__device__ __nv_bfloat16 g_hid_hi[MROWS * HIDC];
__device__ __nv_bfloat16 g_hid_lo[MROWS * HIDC];
// bf16 split weights
__device__ __nv_bfloat16 g_wqkv_hi[1536 * 512], g_wqkv_lo[1536 * 512];
__device__ __nv_bfloat16 g_wprj_hi[512 * 512],  g_wprj_lo[512 * 512];
__device__ __nv_bfloat16 g_w1_hi [2048 * 512],  g_w1_lo [2048 * 512];
__device__ __nv_bfloat16 g_w2_hi [512 * 2048],  g_w2_lo [512 * 2048];

__device__ __forceinline__ uint32_t smem_u32(const void* p) {
    uint32_t a;
    asm("{ .reg .u64 t; cvta.to.shared.u64 t, %1; cvt.u32.u64 %0, t; }"
        : "=r"(a) : "l"(p));
    return a;
}
__device__ __forceinline__ void ldsm_x4(uint32_t& r0, uint32_t& r1,
                                        uint32_t& r2, uint32_t& r3, uint32_t a) {
    asm volatile("ldmatrix.sync.aligned.m8n8.x4.shared.b16 {%0,%1,%2,%3}, [%4];"
                 : "=r"(r0), "=r"(r1), "=r"(r2), "=r"(r3) : "r"(a));
}
__device__ __forceinline__ void mma_bf16(float* d, const uint32_t* a,
                                         uint32_t b0, uint32_t b1) {
    asm volatile("mma.sync.aligned.m16n8k16.row.col.f32.bf16.bf16.f32 "
                 "{%0,%1,%2,%3}, {%4,%5,%6,%7}, {%8,%9}, {%0,%1,%2,%3};"
                 : "+f"(d[0]), "+f"(d[1]), "+f"(d[2]), "+f"(d[3])
                 : "r"(a[0]), "r"(a[1]), "r"(a[2]), "r"(a[3]), "r"(b0), "r"(b1));
}

// ---------------------------------------------------------------------------
// LayerNorm with fused bf16 hi/lo split output
// ---------------------------------------------------------------------------
__global__ void __launch_bounds__(128) ln_split_kernel(
    const float* __restrict__ x, const float* __restrict__ g,
    const float* __restrict__ b,
    __nv_bfloat16* __restrict__ oh, __nv_bfloat16* __restrict__ ol)
{
    int row = blockIdx.x, t = threadIdx.x;
    float4 vv = reinterpret_cast<const float4*>(x + (size_t)row * DIMC)[t];
    float s  = vv.x + vv.y + vv.z + vv.w;
    float sq = vv.x*vv.x + vv.y*vv.y + vv.z*vv.z + vv.w*vv.w;
    #pragma unroll
    for (int o = 16; o > 0; o >>= 1) {
        s  += __shfl_xor_sync(0xffffffffu, s,  o);
        sq += __shfl_xor_sync(0xffffffffu, sq, o);
    }
    __shared__ float ss[4], sq2[4];
    int w = t >> 5;
    if ((t & 31) == 0) { ss[w] = s; sq2[w] = sq; }
    __syncthreads();
    s  = ss[0] + ss[1] + ss[2] + ss[3];
    sq = sq2[0] + sq2[1] + sq2[2] + sq2[3];
    float mu  = s * (1.f / DIMC);
    float var = sq * (1.f / DIMC) - mu * mu;
    float inv = rsqrtf(var + 1e-5f);
    float4 gv = reinterpret_cast<const float4*>(g)[t];
    float4 bv = reinterpret_cast<const float4*>(b)[t];
    float y0 = (vv.x - mu) * inv * gv.x + bv.x;
    float y1 = (vv.y - mu) * inv * gv.y + bv.y;
    float y2 = (vv.z - mu) * inv * gv.z + bv.z;
    float y3 = (vv.w - mu) * inv * gv.w + bv.w;
    __nv_bfloat16 h0 = __float2bfloat16(y0), h1 = __float2bfloat16(y1);
    __nv_bfloat16 h2 = __float2bfloat16(y2), h3 = __float2bfloat16(y3);
    __nv_bfloat162 a01, a23, b01, b23;
    a01.x = h0; a01.y = h1; a23.x = h2; a23.y = h3;
    b01.x = __float2bfloat16(y0 - __bfloat162float(h0));
    b01.y = __float2bfloat16(y1 - __bfloat162float(h1));
    b23.x = __float2bfloat16(y2 - __bfloat162float(h2));
    b23.y = __float2bfloat16(y3 - __bfloat162float(h3));
    __nv_bfloat162* ph = (__nv_bfloat162*)(oh + (size_t)row * DIMC + t * 4);
    __nv_bfloat162* pl = (__nv_bfloat162*)(ol + (size_t)row * DIMC + t * 4);
    ph[0] = a01; ph[1] = a23; pl[0] = b01; pl[1] = b23;
}

// generic fp32 -> bf16 hi/lo split
__global__ void __launch_bounds__(256) split_kernel(
    const float* __restrict__ in, __nv_bfloat16* __restrict__ oh,
    __nv_bfloat16* __restrict__ ol, int n4)
{
    int i = blockIdx.x * 256 + threadIdx.x;
    if (i >= n4) return;
    float4 v = reinterpret_cast<const float4*>(in)[i];
    __nv_bfloat16 h0 = __float2bfloat16(v.x), h1 = __float2bfloat16(v.y);
    __nv_bfloat16 h2 = __float2bfloat16(v.z), h3 = __float2bfloat16(v.w);
    __nv_bfloat162 a01, a23, b01, b23;
    a01.x = h0; a01.y = h1; a23.x = h2; a23.y = h3;
    b01.x = __float2bfloat16(v.x - __bfloat162float(h0));
    b01.y = __float2bfloat16(v.y - __bfloat162float(h1));
    b23.x = __float2bfloat16(v.z - __bfloat162float(h2));
    b23.y = __float2bfloat16(v.w - __bfloat162float(h3));
    ((__nv_bfloat162*)oh)[2 * i] = a01; ((__nv_bfloat162*)oh)[2 * i + 1] = a23;
    ((__nv_bfloat162*)ol)[2 * i] = b01; ((__nv_bfloat162*)ol)[2 * i + 1] = b23;
}

// ---------------------------------------------------------------------------
// Warp-MMA GEMM: C[M,N] = A[M,K] @ B[N,K]^T, bf16x3 split.
// CTA 128x128, K-chunks of 32. 8 warps, warp tile 64x32 (4x4 m16n8k16 atoms).
// SMEM tiles padded: row stride 40 bf16 (80B).
// ---------------------------------------------------------------------------
enum { EPI_QKV = 0, EPI_PROJ = 1, EPI_GELU = 2, EPI_OUT = 3 };

#define LDT 40           // smem row stride (elements)
#define OFF_AH 0
#define OFF_AL 10240
#define OFF_BH 20480
#define OFF_BL 30720

template<int KTOT, int EPI>
__global__ void __launch_bounds__(256) mma_gemm(
    const __nv_bfloat16* __restrict__ Ah, const __nv_bfloat16* __restrict__ Al,
    const __nv_bfloat16* __restrict__ Bh, const __nv_bfloat16* __restrict__ Bl,
    const float* __restrict__ bias, const float* __restrict__ resid,
    float* __restrict__ out0, float* __restrict__ out1, float* __restrict__ out2,
    __nv_bfloat16* __restrict__ obh, __nv_bfloat16* __restrict__ obl, int N)
{
    __shared__ __align__(128) char smem[40960];
    uint32_t sb = smem_u32(smem);
    int t = threadIdx.x, wid = t >> 5, lane = t & 31;
    int m0 = blockIdx.y << 7, n0 = blockIdx.x << 7;
    int warp_m = wid & 1, warp_n = wid >> 1;

    float acc[4][4][4];
    #pragma unroll
    for (int i = 0; i < 4; i++)
        #pragma unroll
        for (int j = 0; j < 4; j++)
            #pragma unroll
            for (int r = 0; r < 4; r++) acc[i][j][r] = 0.f;

    // ldmatrix per-lane base offsets (elements): row = lane&15, colblk = lane>>4
    int lrow = lane & 15, lcb = (lane >> 4) << 3;

    for (int k0 = 0; k0 < KTOT; k0 += 32) {
        // fill tiles: 128 rows x 32 cols each (A hi/lo, B hi/lo)
        #pragma unroll
        for (int i = t; i < 512; i += 256) {
            int r = i >> 2, q = i & 3;
            size_t ga = (size_t)(m0 + r) * KTOT + k0 + q * 8;
            size_t gb = (size_t)(n0 + r) * KTOT + k0 + q * 8;
            uint32_t off = (uint32_t)(r * LDT + q * 8) * 2;
            *(uint4*)(smem + OFF_AH + off) = *(const uint4*)(Ah + ga);
            *(uint4*)(smem + OFF_AL + off) = *(const uint4*)(Al + ga);
            *(uint4*)(smem + OFF_BH + off) = *(const uint4*)(Bh + gb);
            *(uint4*)(smem + OFF_BL + off) = *(const uint4*)(Bl + gb);
        }
        __syncthreads();

        #pragma unroll
        for (int k16 = 0; k16 < 2; k16++) {
            uint32_t afh[4][4], afl[4][4], bfh[2][4], bfl[2][4];
            int col = k16 * 16 + lcb;
            #pragma unroll
            for (int am = 0; am < 4; am++) {
                uint32_t off = (uint32_t)((warp_m * 64 + am * 16 + lrow) * LDT + col) * 2;
                ldsm_x4(afh[am][0], afh[am][1], afh[am][2], afh[am][3], sb + OFF_AH + off);
                ldsm_x4(afl[am][0], afl[am][1], afl[am][2], afl[am][3], sb + OFF_AL + off);
            }
            #pragma unroll
            for (int an2 = 0; an2 < 2; an2++) {
                uint32_t off = (uint32_t)((warp_n * 32 + an2 * 16 + lrow) * LDT + col) * 2;
                ldsm_x4(bfh[an2][0], bfh[an2][1], bfh[an2][2], bfh[an2][3], sb + OFF_BH + off);
                ldsm_x4(bfl[an2][0], bfl[an2][1], bfl[an2][2], bfl[an2][3], sb + OFF_BL + off);
            }
            #pragma unroll
            for (int am = 0; am < 4; am++)
                #pragma unroll
                for (int an = 0; an < 4; an++) {
                    int a2 = an >> 1, p = an & 1;
                    mma_bf16(acc[am][an], afh[am], bfh[a2][p], bfh[a2][p + 2]);
                    mma_bf16(acc[am][an], afh[am], bfl[a2][p], bfl[a2][p + 2]);
                    mma_bf16(acc[am][an], afl[am], bfh[a2][p], bfh[a2][p + 2]);
                }
        }
        __syncthreads();
    }

    // Epilogue: stage 128x64 col-halves through SMEM for coalesced stores
    float* stage = (float*)smem;   // [128][68]
    #pragma unroll 1
    for (int hp = 0; hp < 2; hp++) {
        if ((warp_n >> 1) == hp) {
            #pragma unroll
            for (int am = 0; am < 4; am++) {
                int rb = warp_m * 64 + am * 16 + (lane >> 2);
                #pragma unroll
                for (int an = 0; an < 4; an++) {
                    int c = (warp_n & 1) * 32 + an * 8 + (lane & 3) * 2;
                    stage[rb * 68 + c]           = acc[am][an][0];
                    stage[rb * 68 + c + 1]       = acc[am][an][1];
                    stage[(rb + 8) * 68 + c]     = acc[am][an][2];
                    stage[(rb + 8) * 68 + c + 1] = acc[am][an][3];
                }
            }
        }
        __syncthreads();
        for (int i = t; i < 2048; i += 256) {
            int row = i >> 4, c4 = (i & 15) << 2;
            float v0 = stage[row * 68 + c4 + 0];
            float v1 = stage[row * 68 + c4 + 1];
            float v2 = stage[row * 68 + c4 + 2];
            float v3 = stage[row * 68 + c4 + 3];
            int m = m0 + row;
            int n = n0 + hp * 64 + c4;
            if (EPI == EPI_QKV) {
                int sec = n >> 9, hh = (n >> 6) & 7, dd = n & 63;
                int bb = m >> 10, tok = m & 1023;
                float* dst = (sec == 0) ? out0 : ((sec == 1) ? out1 : out2);
                float4 ov; ov.x = v0; ov.y = v1; ov.z = v2; ov.w = v3;
                *(float4*)(dst + (((size_t)bb * 8 + hh) * 1024 + tok) * 64 + dd) = ov;
            } else if (EPI == EPI_PROJ || EPI == EPI_OUT) {
                float4 rv = *(const float4*)(resid + (size_t)m * N + n);
                float4 bv = *(const float4*)(bias + n);
                float4 ov;
                ov.x = rv.x + v0 + bv.x; ov.y = rv.y + v1 + bv.y;
                ov.z = rv.z + v2 + bv.z; ov.w = rv.w + v3 + bv.w;
                *(float4*)(out0 + (size_t)m * N + n) = ov;
            } else { // EPI_GELU -> bf16 hi/lo split
                float4 bv = *(const float4*)(bias + n);
                float u0 = v0 + bv.x, u1 = v1 + bv.y, u2 = v2 + bv.z, u3 = v3 + bv.w;
                float g0 = 0.5f * u0 * (1.f + erff(u0 * 0.70710678118654752f));
                float g1 = 0.5f * u1 * (1.f + erff(u1 * 0.70710678118654752f));
                float g2 = 0.5f * u2 * (1.f + erff(u2 * 0.70710678118654752f));
                float g3 = 0.5f * u3 * (1.f + erff(u3 * 0.70710678118654752f));
                __nv_bfloat16 h0 = __float2bfloat16(g0), h1 = __float2bfloat16(g1);
                __nv_bfloat16 h2 = __float2bfloat16(g2), h3 = __float2bfloat16(g3);
                __nv_bfloat162 a01, a23, c01, c23;
                a01.x = h0; a01.y = h1; a23.x = h2; a23.y = h3;
                c01.x = __float2bfloat16(g0 - __bfloat162float(h0));
                c01.y = __float2bfloat16(g1 - __bfloat162float(h1));
                c23.x = __float2bfloat16(g2 - __bfloat162float(h2));
                c23.y = __float2bfloat16(g3 - __bfloat162float(h3));
                __nv_bfloat162* ph = (__nv_bfloat162*)(obh + (size_t)m * HIDC + n);
                __nv_bfloat162* pl = (__nv_bfloat162*)(obl + (size_t)m * HIDC + n);
                ph[0] = a01; ph[1] = a23; pl[0] = c01; pl[1] = c23;
            }
        }
        __syncthreads();
    }
}

// ---------------------------------------------------------------------------
// Fused flash attention (fp32) with clipped relative-position bias
// ---------------------------------------------------------------------------
#define ATTN_SMEM_BYTES (16896 * 4)

__global__ void __launch_bounds__(256) attn_kernel(
    const float* __restrict__ q, const float* __restrict__ k,
    const float* __restrict__ v, const float* __restrict__ btab_g,
    float* __restrict__ o)
{
    extern __shared__ float sm[];
    float* qs   = sm;
    float* ks   = sm + 4096;
    float* vs   = sm + 8192;
    float* sbuf = sm + 12288;
    float* btab = sm + 16448;
    float* mrow = sm + 16704;
    float* lrow = sm + 16768;
    float* arow = sm + 16832;

    int qt = blockIdx.x, bh = blockIdx.y;
    int hh = bh & 7;
    int t = threadIdx.x;
    int ty = t >> 4, tx = t & 15;
    int r0 = ty * 4, c0 = tx * 4;

    for (int i = t; i < 225; i += 256) btab[i] = btab_g[i * 8 + hh];

    const float* qbase = q + ((size_t)bh * 1024 + qt * 64) * 64;
    #pragma unroll
    for (int r = 0; r < 4; r++) {
        int idx = t + 256 * r;
        int row = idx >> 4;
        int d4  = (idx & 15) << 2;
        float4 qv = *(const float4*)(qbase + row * 64 + d4);
        qs[(d4+0)*64+row] = qv.x; qs[(d4+1)*64+row] = qv.y;
        qs[(d4+2)*64+row] = qv.z; qs[(d4+3)*64+row] = qv.w;
    }
    if (t < 64) { mrow[t] = -1e30f; lrow[t] = 0.f; }
    float oacc[4][4] = {};
    __syncthreads();

    for (int kt = 0; kt < 16; kt++) {
        const float* kbp = k + ((size_t)bh * 1024 + kt * 64) * 64;
        const float* vbp = v + ((size_t)bh * 1024 + kt * 64) * 64;
        #pragma unroll
        for (int r = 0; r < 4; r++) {
            int idx = t + 256 * r;
            int row = idx >> 4;
            int d4  = (idx & 15) << 2;
            float4 kv = *(const float4*)(kbp + row * 64 + d4);
            ks[(d4+0)*64+row] = kv.x; ks[(d4+1)*64+row] = kv.y;
            ks[(d4+2)*64+row] = kv.z; ks[(d4+3)*64+row] = kv.w;
            float4 vv = *(const float4*)(vbp + row * 64 + d4);
            *(float4*)&vs[row * 64 + d4] = vv;
        }
        __syncthreads();

        float s[4][4] = {};
        #pragma unroll
        for (int d = 0; d < 64; d++) {
            float4 av = *(float4*)&qs[d * 64 + r0];
            float4 bv = *(float4*)&ks[d * 64 + c0];
            float a_[4] = {av.x, av.y, av.z, av.w};
            float b_[4] = {bv.x, bv.y, bv.z, bv.w};
            #pragma unroll
            for (int i = 0; i < 4; i++)
                #pragma unroll
                for (int j = 0; j < 4; j++)
                    s[i][j] += a_[i] * b_[j];
        }
        int qi0 = qt * 64 + r0, kj0 = kt * 64 + c0;
        #pragma unroll
        for (int i = 0; i < 4; i++) {
            int qi = qi0 + i;
            int qy = qi >> 5, qx = qi & 31;
            #pragma unroll
            for (int j = 0; j < 4; j++) {
                int kj = kj0 + j;
                int dy = qy - (kj >> 5) + 31;
                int dx = qx - (kj & 31) + 31;
                int id = dy * 63 + dx;
                id = id < 224 ? id : 224;
                sbuf[(r0 + i) * 65 + c0 + j] = s[i][j] * 0.125f + btab[id];
            }
        }
        __syncthreads();

        if (t < 64) {
            float* row = &sbuf[t * 65];
            float mold = mrow[t];
            float tm = mold;
            #pragma unroll
            for (int j = 0; j < 64; j++) tm = fmaxf(tm, row[j]);
            float alpha = __expf(mold - tm);
            float sum = 0.f;
            #pragma unroll
            for (int j = 0; j < 64; j++) {
                float e = __expf(row[j] - tm);
                row[j] = e;
                sum += e;
            }
            lrow[t] = lrow[t] * alpha + sum;
            mrow[t] = tm;
            arow[t] = alpha;
        }
        __syncthreads();

        #pragma unroll
        for (int i = 0; i < 4; i++) {
            float al = arow[r0 + i];
            #pragma unroll
            for (int j = 0; j < 4; j++) oacc[i][j] *= al;
        }
        #pragma unroll
        for (int kk = 0; kk < 64; kk++) {
            float4 vv = *(float4*)&vs[kk * 64 + c0];
            float vb[4] = {vv.x, vv.y, vv.z, vv.w};
            #pragma unroll
            for (int i = 0; i < 4; i++) {
                float p = sbuf[(r0 + i) * 65 + kk];
                #pragma unroll
                for (int j = 0; j < 4; j++) oacc[i][j] += p * vb[j];
            }
        }
        __syncthreads();
    }

    int bb = bh >> 3;
    #pragma unroll
    for (int i = 0; i < 4; i++) {
        int row = r0 + i;
        float inv = 1.f / lrow[row];
        int tok = qt * 64 + row;
        float4 ov;
        ov.x = oacc[i][0] * inv; ov.y = oacc[i][1] * inv;
        ov.z = oacc[i][2] * inv; ov.w = oacc[i][3] * inv;
        *(float4*)(o + ((size_t)bb * 1024 + tok) * 512 + hh * 64 + c0) = ov;
    }
}

// ---------------------------------------------------------------------------
// Launcher
// ---------------------------------------------------------------------------
extern "C" void kernel_launch(void* const* d_in, const int* in_sizes, int n_in,
                              void* d_out, int out_size)
{
    const float* x      = (const float*)d_in[0];
    const float* qkv_w  = (const float*)d_in[1];
    const float* proj_w = (const float*)d_in[2];
    const float* proj_b = (const float*)d_in[3];
    const float* mlp_w1 = (const float*)d_in[4];
    const float* mlp_b1 = (const float*)d_in[5];
    const float* mlp_w2 = (const float*)d_in[6];
    const float* mlp_b2 = (const float*)d_in[7];
    const float* n1g    = (const float*)d_in[8];
    const float* n1b    = (const float*)d_in[9];
    const float* n2g    = (const float*)d_in[10];
    const float* n2b    = (const float*)d_in[11];
    const float* btab   = (const float*)d_in[12];
    float* out = (float*)d_out;

    float *q, *k, *v, *o, *x1;
    cudaGetSymbolAddress((void**)&q,  d_q);
    cudaGetSymbolAddress((void**)&k,  d_k);
    cudaGetSymbolAddress((void**)&v,  d_v);
    cudaGetSymbolAddress((void**)&o,  d_o);
    cudaGetSymbolAddress((void**)&x1, d_x1);
    __nv_bfloat16 *hh_, *hl_, *ohh, *ohl, *hidh, *hidl;
    __nv_bfloat16 *wqh, *wql, *wph, *wpl, *w1h, *w1l, *w2h, *w2l;
    cudaGetSymbolAddress((void**)&hh_,  g_h_hi);
    cudaGetSymbolAddress((void**)&hl_,  g_h_lo);
    cudaGetSymbolAddress((void**)&ohh,  g_o_hi);
    cudaGetSymbolAddress((void**)&ohl,  g_o_lo);
    cudaGetSymbolAddress((void**)&hidh, g_hid_hi);
    cudaGetSymbolAddress((void**)&hidl, g_hid_lo);
    cudaGetSymbolAddress((void**)&wqh,  g_wqkv_hi);
    cudaGetSymbolAddress((void**)&wql,  g_wqkv_lo);
    cudaGetSymbolAddress((void**)&wph,  g_wprj_hi);
    cudaGetSymbolAddress((void**)&wpl,  g_wprj_lo);
    cudaGetSymbolAddress((void**)&w1h,  g_w1_hi);
    cudaGetSymbolAddress((void**)&w1l,  g_w1_lo);
    cudaGetSymbolAddress((void**)&w2h,  g_w2_hi);
    cudaGetSymbolAddress((void**)&w2l,  g_w2_lo);

    cudaFuncSetAttribute(attn_kernel,
        cudaFuncAttributeMaxDynamicSharedMemorySize, ATTN_SMEM_BYTES);

    // weight splits
    split_kernel<<<(1536 * 512 / 4 + 255) / 256, 256>>>(qkv_w,  wqh, wql, 1536 * 512 / 4);
    split_kernel<<<(512 * 512 / 4 + 255) / 256, 256>>>(proj_w, wph, wpl, 512 * 512 / 4);
    split_kernel<<<(2048 * 512 / 4 + 255) / 256, 256>>>(mlp_w1, w1h, w1l, 2048 * 512 / 4);
    split_kernel<<<(512 * 2048 / 4 + 255) / 256, 256>>>(mlp_w2, w2h, w2l, 512 * 2048 / 4);

    // LN1 -> split
    ln_split_kernel<<<MROWS, 128>>>(x, n1g, n1b, hh_, hl_);
    // QKV (N=1536)
    mma_gemm<512, EPI_QKV><<<dim3(12, 256), 256>>>(
        hh_, hl_, wqh, wql, nullptr, nullptr, q, k, v, nullptr, nullptr, 1536);
    // attention
    attn_kernel<<<dim3(16, 256), 256, ATTN_SMEM_BYTES>>>(q, k, v, btab, o);
    // split o
    split_kernel<<<(MROWS * DIMC / 4 + 255) / 256, 256>>>(o, ohh, ohl, MROWS * DIMC / 4);
    // proj + residual (N=512)
    mma_gemm<512, EPI_PROJ><<<dim3(4, 256), 256>>>(
        ohh, ohl, wph, wpl, proj_b, x, x1, nullptr, nullptr, nullptr, nullptr, 512);
    // LN2 -> split
    ln_split_kernel<<<MROWS, 128>>>(x1, n2g, n2b, hh_, hl_);
    // MLP1 + GELU (N=2048)
    mma_gemm<512, EPI_GELU><<<dim3(16, 256), 256>>>(
        hh_, hl_, w1h, w1l, mlp_b1, nullptr, nullptr, nullptr, nullptr, hidh, hidl, 2048);
    // MLP2 + residual -> out (N=512, K=2048)
    mma_gemm<2048, EPI_OUT><<<dim3(4, 256), 256>>>(
        hidh, hidl, w2h, w2l, mlp_b2, x1, out, nullptr, nullptr, nullptr, nullptr, 512);
}

// round 5
// speedup vs baseline: 2.3011x; 1.4758x over previous
#include <cuda_runtime.h>
#include <cuda_bf16.h>
#include <math.h>
#include <stdint.h>

// ---------------------------------------------------------------------------
// B=32, N=1024, DIM=512, HEADS=8, HEAD_DIM=64, MLP_HIDDEN=2048. M = 32768.
// All GEMMs + attention on mma.sync bf16 (bf16x3 split => fp32-class accuracy).
// Harness PTX target is compute_103 (no 'a') -> no tcgen05/TMA available.
// ---------------------------------------------------------------------------
#define MROWS 32768
#define DIMC  512
#define HIDC  2048

// fp32 scratch
__device__ float d_x1[MROWS * DIMC];
// bf16 split activations
__device__ __nv_bfloat16 g_h_hi [MROWS * DIMC];
__device__ __nv_bfloat16 g_h_lo [MROWS * DIMC];
__device__ __nv_bfloat16 g_o_hi [MROWS * DIMC];
__device__ __nv_bfloat16 g_o_lo [MROWS * DIMC];
__device__ __nv_bfloat16 g_hid_hi[MROWS * HIDC];
__device__ __nv_bfloat16 g_hid_lo[MROWS * HIDC];
// q/k/v bf16 hi/lo, layout [B*H][1024][64]
__device__ __nv_bfloat16 g_qh[MROWS * DIMC], g_ql[MROWS * DIMC];
__device__ __nv_bfloat16 g_kh[MROWS * DIMC], g_kl[MROWS * DIMC];
__device__ __nv_bfloat16 g_vh[MROWS * DIMC], g_vl[MROWS * DIMC];
// bf16 split weights
__device__ __nv_bfloat16 g_wqkv_hi[1536 * 512], g_wqkv_lo[1536 * 512];
__device__ __nv_bfloat16 g_wprj_hi[512 * 512],  g_wprj_lo[512 * 512];
__device__ __nv_bfloat16 g_w1_hi [2048 * 512],  g_w1_lo [2048 * 512];
__device__ __nv_bfloat16 g_w2_hi [512 * 2048],  g_w2_lo [512 * 2048];

__device__ __forceinline__ uint32_t smem_u32(const void* p) {
    uint32_t a;
    asm("{ .reg .u64 t; cvta.to.shared.u64 t, %1; cvt.u32.u64 %0, t; }"
        : "=r"(a) : "l"(p));
    return a;
}
__device__ __forceinline__ void ldsm_x4(uint32_t& r0, uint32_t& r1,
                                        uint32_t& r2, uint32_t& r3, uint32_t a) {
    asm volatile("ldmatrix.sync.aligned.m8n8.x4.shared.b16 {%0,%1,%2,%3}, [%4];"
                 : "=r"(r0), "=r"(r1), "=r"(r2), "=r"(r3) : "r"(a));
}
__device__ __forceinline__ void mma_bf16(float* d, const uint32_t* a,
                                         uint32_t b0, uint32_t b1) {
    asm volatile("mma.sync.aligned.m16n8k16.row.col.f32.bf16.bf16.f32 "
                 "{%0,%1,%2,%3}, {%4,%5,%6,%7}, {%8,%9}, {%0,%1,%2,%3};"
                 : "+f"(d[0]), "+f"(d[1]), "+f"(d[2]), "+f"(d[3])
                 : "r"(a[0]), "r"(a[1]), "r"(a[2]), "r"(a[3]), "r"(b0), "r"(b1));
}
__device__ __forceinline__ void pack_hl(float x, float y, uint32_t& hi, uint32_t& lo) {
    __nv_bfloat16 hx = __float2bfloat16(x), hy = __float2bfloat16(y);
    __nv_bfloat162 H; H.x = hx; H.y = hy;
    __nv_bfloat162 L;
    L.x = __float2bfloat16(x - __bfloat162float(hx));
    L.y = __float2bfloat16(y - __bfloat162float(hy));
    hi = *(uint32_t*)&H; lo = *(uint32_t*)&L;
}

// ---------------------------------------------------------------------------
// LayerNorm with fused bf16 hi/lo split output
// ---------------------------------------------------------------------------
__global__ void __launch_bounds__(128) ln_split_kernel(
    const float* __restrict__ x, const float* __restrict__ g,
    const float* __restrict__ b,
    __nv_bfloat16* __restrict__ oh, __nv_bfloat16* __restrict__ ol)
{
    int row = blockIdx.x, t = threadIdx.x;
    float4 vv = reinterpret_cast<const float4*>(x + (size_t)row * DIMC)[t];
    float s  = vv.x + vv.y + vv.z + vv.w;
    float sq = vv.x*vv.x + vv.y*vv.y + vv.z*vv.z + vv.w*vv.w;
    #pragma unroll
    for (int o = 16; o > 0; o >>= 1) {
        s  += __shfl_xor_sync(0xffffffffu, s,  o);
        sq += __shfl_xor_sync(0xffffffffu, sq, o);
    }
    __shared__ float ss[4], sq2[4];
    int w = t >> 5;
    if ((t & 31) == 0) { ss[w] = s; sq2[w] = sq; }
    __syncthreads();
    s  = ss[0] + ss[1] + ss[2] + ss[3];
    sq = sq2[0] + sq2[1] + sq2[2] + sq2[3];
    float mu  = s * (1.f / DIMC);
    float var = sq * (1.f / DIMC) - mu * mu;
    float inv = rsqrtf(var + 1e-5f);
    float4 gv = reinterpret_cast<const float4*>(g)[t];
    float4 bv = reinterpret_cast<const float4*>(b)[t];
    float y0 = (vv.x - mu) * inv * gv.x + bv.x;
    float y1 = (vv.y - mu) * inv * gv.y + bv.y;
    float y2 = (vv.z - mu) * inv * gv.z + bv.z;
    float y3 = (vv.w - mu) * inv * gv.w + bv.w;
    uint32_t h01, l01, h23, l23;
    pack_hl(y0, y1, h01, l01);
    pack_hl(y2, y3, h23, l23);
    uint2 uh; uh.x = h01; uh.y = h23;
    uint2 ul; ul.x = l01; ul.y = l23;
    *(uint2*)(oh + (size_t)row * DIMC + t * 4) = uh;
    *(uint2*)(ol + (size_t)row * DIMC + t * 4) = ul;
}

// generic fp32 -> bf16 hi/lo split (weights)
__global__ void __launch_bounds__(256) split_kernel(
    const float* __restrict__ in, __nv_bfloat16* __restrict__ oh,
    __nv_bfloat16* __restrict__ ol, int n4)
{
    int i = blockIdx.x * 256 + threadIdx.x;
    if (i >= n4) return;
    float4 v = reinterpret_cast<const float4*>(in)[i];
    uint32_t h01, l01, h23, l23;
    pack_hl(v.x, v.y, h01, l01);
    pack_hl(v.z, v.w, h23, l23);
    uint2 uh; uh.x = h01; uh.y = h23;
    uint2 ul; ul.x = l01; ul.y = l23;
    *(uint2*)(oh + (size_t)i * 4) = uh;
    *(uint2*)(ol + (size_t)i * 4) = ul;
}

// ---------------------------------------------------------------------------
// Warp-MMA GEMM: C[M,N] = A[M,K] @ B[N,K]^T, bf16x3 split.
// CTA 128x128, K-chunks of 32. 8 warps, warp tile 64x32.
// ---------------------------------------------------------------------------
enum { EPI_QKV = 0, EPI_PROJ = 1, EPI_GELU = 2, EPI_OUT = 3 };

#define LDT 40
#define OFF_AH 0
#define OFF_AL 10240
#define OFF_BH 20480
#define OFF_BL 30720

template<int KTOT, int EPI>
__global__ void __launch_bounds__(256) mma_gemm(
    const __nv_bfloat16* __restrict__ Ah, const __nv_bfloat16* __restrict__ Al,
    const __nv_bfloat16* __restrict__ Bh, const __nv_bfloat16* __restrict__ Bl,
    const float* __restrict__ bias, const float* __restrict__ resid,
    float* __restrict__ out0,
    __nv_bfloat16* __restrict__ obh, __nv_bfloat16* __restrict__ obl,
    __nv_bfloat16* __restrict__ oqh, __nv_bfloat16* __restrict__ oql,
    __nv_bfloat16* __restrict__ okh, __nv_bfloat16* __restrict__ okl,
    __nv_bfloat16* __restrict__ ovh, __nv_bfloat16* __restrict__ ovl, int N)
{
    __shared__ __align__(128) char smem[40960];
    uint32_t sb = smem_u32(smem);
    int t = threadIdx.x, wid = t >> 5, lane = t & 31;
    int m0 = blockIdx.y << 7, n0 = blockIdx.x << 7;
    int warp_m = wid & 1, warp_n = wid >> 1;

    float acc[4][4][4];
    #pragma unroll
    for (int i = 0; i < 4; i++)
        #pragma unroll
        for (int j = 0; j < 4; j++)
            #pragma unroll
            for (int r = 0; r < 4; r++) acc[i][j][r] = 0.f;

    int lrow = lane & 15, lcb = (lane >> 4) << 3;

    for (int k0 = 0; k0 < KTOT; k0 += 32) {
        #pragma unroll
        for (int i = t; i < 512; i += 256) {
            int r = i >> 2, q = i & 3;
            size_t ga = (size_t)(m0 + r) * KTOT + k0 + q * 8;
            size_t gb = (size_t)(n0 + r) * KTOT + k0 + q * 8;
            uint32_t off = (uint32_t)(r * LDT + q * 8) * 2;
            *(uint4*)(smem + OFF_AH + off) = *(const uint4*)(Ah + ga);
            *(uint4*)(smem + OFF_AL + off) = *(const uint4*)(Al + ga);
            *(uint4*)(smem + OFF_BH + off) = *(const uint4*)(Bh + gb);
            *(uint4*)(smem + OFF_BL + off) = *(const uint4*)(Bl + gb);
        }
        __syncthreads();

        #pragma unroll
        for (int k16 = 0; k16 < 2; k16++) {
            uint32_t afh[4][4], afl[4][4], bfh[2][4], bfl[2][4];
            int col = k16 * 16 + lcb;
            #pragma unroll
            for (int am = 0; am < 4; am++) {
                uint32_t off = (uint32_t)((warp_m * 64 + am * 16 + lrow) * LDT + col) * 2;
                ldsm_x4(afh[am][0], afh[am][1], afh[am][2], afh[am][3], sb + OFF_AH + off);
                ldsm_x4(afl[am][0], afl[am][1], afl[am][2], afl[am][3], sb + OFF_AL + off);
            }
            #pragma unroll
            for (int an2 = 0; an2 < 2; an2++) {
                uint32_t off = (uint32_t)((warp_n * 32 + an2 * 16 + lrow) * LDT + col) * 2;
                ldsm_x4(bfh[an2][0], bfh[an2][1], bfh[an2][2], bfh[an2][3], sb + OFF_BH + off);
                ldsm_x4(bfl[an2][0], bfl[an2][1], bfl[an2][2], bfl[an2][3], sb + OFF_BL + off);
            }
            #pragma unroll
            for (int am = 0; am < 4; am++)
                #pragma unroll
                for (int an = 0; an < 4; an++) {
                    int a2 = an >> 1, p = an & 1;
                    mma_bf16(acc[am][an], afh[am], bfh[a2][p], bfh[a2][p + 2]);
                    mma_bf16(acc[am][an], afh[am], bfl[a2][p], bfl[a2][p + 2]);
                    mma_bf16(acc[am][an], afl[am], bfh[a2][p], bfh[a2][p + 2]);
                }
        }
        __syncthreads();
    }

    float* stage = (float*)smem;   // [128][68]
    #pragma unroll 1
    for (int hp = 0; hp < 2; hp++) {
        if ((warp_n >> 1) == hp) {
            #pragma unroll
            for (int am = 0; am < 4; am++) {
                int rb = warp_m * 64 + am * 16 + (lane >> 2);
                #pragma unroll
                for (int an = 0; an < 4; an++) {
                    int c = (warp_n & 1) * 32 + an * 8 + (lane & 3) * 2;
                    stage[rb * 68 + c]           = acc[am][an][0];
                    stage[rb * 68 + c + 1]       = acc[am][an][1];
                    stage[(rb + 8) * 68 + c]     = acc[am][an][2];
                    stage[(rb + 8) * 68 + c + 1] = acc[am][an][3];
                }
            }
        }
        __syncthreads();
        for (int i = t; i < 2048; i += 256) {
            int row = i >> 4, c4 = (i & 15) << 2;
            float v0 = stage[row * 68 + c4 + 0];
            float v1 = stage[row * 68 + c4 + 1];
            float v2 = stage[row * 68 + c4 + 2];
            float v3 = stage[row * 68 + c4 + 3];
            int m = m0 + row;
            int n = n0 + hp * 64 + c4;
            if (EPI == EPI_QKV) {
                int sec = n >> 9, hd = (n >> 6) & 7, dd = n & 63;
                int bbq = m >> 10, tok = m & 1023;
                size_t di = (((size_t)bbq * 8 + hd) * 1024 + tok) * 64 + dd;
                __nv_bfloat16 *dh, *dl;
                if (sec == 0)      { dh = oqh; dl = oql; }
                else if (sec == 1) { dh = okh; dl = okl; }
                else               { dh = ovh; dl = ovl; }
                uint32_t h01, l01, h23, l23;
                pack_hl(v0, v1, h01, l01);
                pack_hl(v2, v3, h23, l23);
                uint2 uh; uh.x = h01; uh.y = h23;
                uint2 ul; ul.x = l01; ul.y = l23;
                *(uint2*)(dh + di) = uh;
                *(uint2*)(dl + di) = ul;
            } else if (EPI == EPI_PROJ || EPI == EPI_OUT) {
                float4 rv = *(const float4*)(resid + (size_t)m * N + n);
                float4 bv = *(const float4*)(bias + n);
                float4 ov;
                ov.x = rv.x + v0 + bv.x; ov.y = rv.y + v1 + bv.y;
                ov.z = rv.z + v2 + bv.z; ov.w = rv.w + v3 + bv.w;
                *(float4*)(out0 + (size_t)m * N + n) = ov;
            } else { // EPI_GELU -> bf16 hi/lo split
                float4 bv = *(const float4*)(bias + n);
                float u0 = v0 + bv.x, u1 = v1 + bv.y, u2 = v2 + bv.z, u3 = v3 + bv.w;
                float g0 = 0.5f * u0 * (1.f + erff(u0 * 0.70710678118654752f));
                float g1 = 0.5f * u1 * (1.f + erff(u1 * 0.70710678118654752f));
                float g2 = 0.5f * u2 * (1.f + erff(u2 * 0.70710678118654752f));
                float g3 = 0.5f * u3 * (1.f + erff(u3 * 0.70710678118654752f));
                uint32_t h01, l01, h23, l23;
                pack_hl(g0, g1, h01, l01);
                pack_hl(g2, g3, h23, l23);
                uint2 uh; uh.x = h01; uh.y = h23;
                uint2 ul; ul.x = l01; ul.y = l23;
                *(uint2*)(obh + (size_t)m * HIDC + n) = uh;
                *(uint2*)(obl + (size_t)m * HIDC + n) = ul;
            }
        }
        __syncthreads();
    }
}

// ---------------------------------------------------------------------------
// Tensor-core flash attention, bf16 split, rel-pos bias.
// grid = (8 q-blocks of 128 rows, 256 bh). 256 threads (8 warps x 16 rows).
// SMEM: QH 0..18432, QL ..36864, KH ..46080, KL ..55296,
//       VTH ..64512, VTL ..73728 (V transposed [d][seq]), BTAB ..74752, LINV ..75264
// ---------------------------------------------------------------------------
#define A_QH 0u
#define A_QL 18432u
#define A_KH 36864u
#define A_KL 46080u
#define A_VH 55296u
#define A_VL 64512u
#define A_BT 73728u
#define A_LI 74752u
#define ATTN_SMEM 75264

__global__ void __launch_bounds__(256) attn_tc_kernel(
    const __nv_bfloat16* __restrict__ qh_g, const __nv_bfloat16* __restrict__ ql_g,
    const __nv_bfloat16* __restrict__ kh_g, const __nv_bfloat16* __restrict__ kl_g,
    const __nv_bfloat16* __restrict__ vh_g, const __nv_bfloat16* __restrict__ vl_g,
    const float* __restrict__ btab_g,
    __nv_bfloat16* __restrict__ ohh, __nv_bfloat16* __restrict__ ohl)
{
    extern __shared__ char sm_[];
    __nv_bfloat16* sqh = (__nv_bfloat16*)(sm_ + A_QH);
    __nv_bfloat16* sql = (__nv_bfloat16*)(sm_ + A_QL);
    __nv_bfloat16* skh = (__nv_bfloat16*)(sm_ + A_KH);
    __nv_bfloat16* skl = (__nv_bfloat16*)(sm_ + A_KL);
    __nv_bfloat16* svh = (__nv_bfloat16*)(sm_ + A_VH);
    __nv_bfloat16* svl = (__nv_bfloat16*)(sm_ + A_VL);
    float* btab = (float*)(sm_ + A_BT);
    float* linv = (float*)(sm_ + A_LI);
    uint32_t sb = smem_u32(sm_);

    int qb = blockIdx.x, bh = blockIdx.y;
    int hh = bh & 7, bb = bh >> 3;
    int t = threadIdx.x, wid = t >> 5, lane = t & 31;
    int lrow = lane & 15, lcb = (lane >> 4) << 3;

    for (int i = t; i < 225; i += 256) btab[i] = btab_g[i * 8 + hh];

    // load Q 128x64 hi/lo
    {
        const __nv_bfloat16* qbh = qh_g + ((size_t)bh * 1024 + qb * 128) * 64;
        const __nv_bfloat16* qbl = ql_g + ((size_t)bh * 1024 + qb * 128) * 64;
        for (int i = t; i < 1024; i += 256) {
            int r = i >> 3, c8 = (i & 7) * 8;
            *(uint4*)(sqh + r * 72 + c8) = *(const uint4*)(qbh + r * 64 + c8);
            *(uint4*)(sql + r * 72 + c8) = *(const uint4*)(qbl + r * 64 + c8);
        }
    }
    __syncthreads();
    uint32_t qfh[4][4], qfl[4][4];
    #pragma unroll
    for (int k = 0; k < 4; k++) {
        uint32_t off = (uint32_t)((wid * 16 + lrow) * 72 + k * 16 + lcb) * 2;
        ldsm_x4(qfh[k][0], qfh[k][1], qfh[k][2], qfh[k][3], sb + A_QH + off);
        ldsm_x4(qfl[k][0], qfl[k][1], qfl[k][2], qfl[k][3], sb + A_QL + off);
    }

    float oacc[8][4];
    #pragma unroll
    for (int j = 0; j < 8; j++)
        #pragma unroll
        for (int r = 0; r < 4; r++) oacc[j][r] = 0.f;
    float mrow[2] = {-1e30f, -1e30f}, lsum[2] = {0.f, 0.f};

    int trbase = qb * 128 + wid * 16 + (lane >> 2);

    for (int kt = 0; kt < 16; kt++) {
        const __nv_bfloat16* kbh = kh_g + ((size_t)bh * 1024 + kt * 64) * 64;
        const __nv_bfloat16* kbl = kl_g + ((size_t)bh * 1024 + kt * 64) * 64;
        const __nv_bfloat16* vbh = vh_g + ((size_t)bh * 1024 + kt * 64) * 64;
        const __nv_bfloat16* vbl = vl_g + ((size_t)bh * 1024 + kt * 64) * 64;
        __syncthreads();
        for (int i = t; i < 512; i += 256) {
            int r = i >> 3, c8 = (i & 7) * 8;
            *(uint4*)(skh + r * 72 + c8) = *(const uint4*)(kbh + r * 64 + c8);
            *(uint4*)(skl + r * 72 + c8) = *(const uint4*)(kbl + r * 64 + c8);
            uint4 v4h = *(const uint4*)(vbh + r * 64 + c8);
            uint4 v4l = *(const uint4*)(vbl + r * 64 + c8);
            __nv_bfloat16* ph = (__nv_bfloat16*)&v4h;
            __nv_bfloat16* pl = (__nv_bfloat16*)&v4l;
            #pragma unroll
            for (int e = 0; e < 8; e++) {
                svh[(c8 + e) * 72 + r] = ph[e];
                svl[(c8 + e) * 72 + r] = pl[e];
            }
        }
        __syncthreads();

        // S = Q K^T (hi*hi + hi*lo + lo*hi)
        float sacc[8][4];
        #pragma unroll
        for (int j = 0; j < 8; j++)
            #pragma unroll
            for (int r = 0; r < 4; r++) sacc[j][r] = 0.f;
        #pragma unroll
        for (int k = 0; k < 4; k++) {
            uint32_t bkh[4][4], bkl[4][4];
            #pragma unroll
            for (int g = 0; g < 4; g++) {
                uint32_t off = (uint32_t)((g * 16 + lrow) * 72 + k * 16 + lcb) * 2;
                ldsm_x4(bkh[g][0], bkh[g][1], bkh[g][2], bkh[g][3], sb + A_KH + off);
                ldsm_x4(bkl[g][0], bkl[g][1], bkl[g][2], bkl[g][3], sb + A_KL + off);
            }
            #pragma unroll
            for (int j = 0; j < 8; j++) {
                int g = j >> 1, p = j & 1;
                mma_bf16(sacc[j], qfh[k], bkh[g][p], bkh[g][p + 2]);
                mma_bf16(sacc[j], qfh[k], bkl[g][p], bkl[g][p + 2]);
                mma_bf16(sacc[j], qfl[k], bkh[g][p], bkh[g][p + 2]);
            }
        }

        // bias + online softmax
        #pragma unroll
        for (int h = 0; h < 2; h++) {
            int tr = trbase + h * 8;
            int qy = tr >> 5, qx = tr & 31;
            float m = mrow[h];
            #pragma unroll
            for (int j = 0; j < 8; j++) {
                int tc0 = kt * 64 + j * 8 + (lane & 3) * 2;
                int id0 = (qy - (tc0 >> 5) + 31) * 63 + (qx - (tc0 & 31) + 31);
                id0 = id0 < 224 ? id0 : 224;
                int tc1 = tc0 + 1;
                int id1 = (qy - (tc1 >> 5) + 31) * 63 + (qx - (tc1 & 31) + 31);
                id1 = id1 < 224 ? id1 : 224;
                float s0 = sacc[j][h * 2 + 0] * 0.125f + btab[id0];
                float s1 = sacc[j][h * 2 + 1] * 0.125f + btab[id1];
                sacc[j][h * 2 + 0] = s0; sacc[j][h * 2 + 1] = s1;
                m = fmaxf(m, fmaxf(s0, s1));
            }
            m = fmaxf(m, __shfl_xor_sync(0xffffffffu, m, 1));
            m = fmaxf(m, __shfl_xor_sync(0xffffffffu, m, 2));
            float alpha = __expf(mrow[h] - m);
            float sum = 0.f;
            #pragma unroll
            for (int j = 0; j < 8; j++) {
                float e0 = __expf(sacc[j][h * 2 + 0] - m);
                float e1 = __expf(sacc[j][h * 2 + 1] - m);
                sacc[j][h * 2 + 0] = e0; sacc[j][h * 2 + 1] = e1;
                sum += e0 + e1;
            }
            sum += __shfl_xor_sync(0xffffffffu, sum, 1);
            sum += __shfl_xor_sync(0xffffffffu, sum, 2);
            lsum[h] = lsum[h] * alpha + sum;
            mrow[h] = m;
            #pragma unroll
            for (int j = 0; j < 8; j++) {
                oacc[j][h * 2 + 0] *= alpha;
                oacc[j][h * 2 + 1] *= alpha;
            }
        }

        // pack P into A fragments (hi/lo)
        uint32_t aph[4][4], apl[4][4];
        #pragma unroll
        for (int k = 0; k < 4; k++) {
            int j0 = 2 * k, j1 = 2 * k + 1;
            pack_hl(sacc[j0][0], sacc[j0][1], aph[k][0], apl[k][0]);
            pack_hl(sacc[j0][2], sacc[j0][3], aph[k][1], apl[k][1]);
            pack_hl(sacc[j1][0], sacc[j1][1], aph[k][2], apl[k][2]);
            pack_hl(sacc[j1][2], sacc[j1][3], aph[k][3], apl[k][3]);
        }

        // O += P V  (Ph*Vh + Ph*Vl + Pl*Vh), V transposed in smem: [d][seq]
        #pragma unroll
        for (int k = 0; k < 4; k++) {
            uint32_t bvh[4][4], bvl[4][4];
            #pragma unroll
            for (int g = 0; g < 4; g++) {
                uint32_t off = (uint32_t)((g * 16 + lrow) * 72 + k * 16 + lcb) * 2;
                ldsm_x4(bvh[g][0], bvh[g][1], bvh[g][2], bvh[g][3], sb + A_VH + off);
                ldsm_x4(bvl[g][0], bvl[g][1], bvl[g][2], bvl[g][3], sb + A_VL + off);
            }
            #pragma unroll
            for (int j = 0; j < 8; j++) {
                int g = j >> 1, p = j & 1;
                mma_bf16(oacc[j], aph[k], bvh[g][p], bvh[g][p + 2]);
                mma_bf16(oacc[j], aph[k], bvl[g][p], bvl[g][p + 2]);
                mma_bf16(oacc[j], apl[k], bvh[g][p], bvh[g][p + 2]);
            }
        }
    }

    // finalize
    if ((lane & 3) == 0) {
        linv[wid * 16 + (lane >> 2)]     = 1.f / lsum[0];
        linv[wid * 16 + (lane >> 2) + 8] = 1.f / lsum[1];
    }
    __syncwarp();
    float* ow = (float*)sm_ + wid * 16 * 66;   // reuse Q region
    #pragma unroll
    for (int j = 0; j < 8; j++) {
        int c = j * 8 + (lane & 3) * 2;
        int r = lane >> 2;
        ow[r * 66 + c]           = oacc[j][0];
        ow[r * 66 + c + 1]       = oacc[j][1];
        ow[(r + 8) * 66 + c]     = oacc[j][2];
        ow[(r + 8) * 66 + c + 1] = oacc[j][3];
    }
    __syncwarp();
    for (int i = lane; i < 256; i += 32) {
        int r = i >> 4, cg = (i & 15) * 4;
        float inv = linv[wid * 16 + r];
        float v0 = ow[r * 66 + cg]     * inv;
        float v1 = ow[r * 66 + cg + 1] * inv;
        float v2 = ow[r * 66 + cg + 2] * inv;
        float v3 = ow[r * 66 + cg + 3] * inv;
        uint32_t h01, l01, h23, l23;
        pack_hl(v0, v1, h01, l01);
        pack_hl(v2, v3, h23, l23);
        size_t go = ((size_t)bb * 1024 + qb * 128 + wid * 16 + r) * 512 + hh * 64 + cg;
        uint2 uh; uh.x = h01; uh.y = h23;
        uint2 ul; ul.x = l01; ul.y = l23;
        *(uint2*)(ohh + go) = uh;
        *(uint2*)(ohl + go) = ul;
    }
}

// ---------------------------------------------------------------------------
// Launcher
// ---------------------------------------------------------------------------
extern "C" void kernel_launch(void* const* d_in, const int* in_sizes, int n_in,
                              void* d_out, int out_size)
{
    const float* x      = (const float*)d_in[0];
    const float* qkv_w  = (const float*)d_in[1];
    const float* proj_w = (const float*)d_in[2];
    const float* proj_b = (const float*)d_in[3];
    const float* mlp_w1 = (const float*)d_in[4];
    const float* mlp_b1 = (const float*)d_in[5];
    const float* mlp_w2 = (const float*)d_in[6];
    const float* mlp_b2 = (const float*)d_in[7];
    const float* n1g    = (const float*)d_in[8];
    const float* n1b    = (const float*)d_in[9];
    const float* n2g    = (const float*)d_in[10];
    const float* n2b    = (const float*)d_in[11];
    const float* btab   = (const float*)d_in[12];
    float* out = (float*)d_out;

    float* x1;
    cudaGetSymbolAddress((void**)&x1, d_x1);
    __nv_bfloat16 *hh_, *hl_, *ohh, *ohl, *hidh, *hidl;
    __nv_bfloat16 *qh, *ql, *kh, *kl, *vh, *vl;
    __nv_bfloat16 *wqh, *wql, *wph, *wpl, *w1h, *w1l, *w2h, *w2l;
    cudaGetSymbolAddress((void**)&hh_,  g_h_hi);
    cudaGetSymbolAddress((void**)&hl_,  g_h_lo);
    cudaGetSymbolAddress((void**)&ohh,  g_o_hi);
    cudaGetSymbolAddress((void**)&ohl,  g_o_lo);
    cudaGetSymbolAddress((void**)&hidh, g_hid_hi);
    cudaGetSymbolAddress((void**)&hidl, g_hid_lo);
    cudaGetSymbolAddress((void**)&qh, g_qh); cudaGetSymbolAddress((void**)&ql, g_ql);
    cudaGetSymbolAddress((void**)&kh, g_kh); cudaGetSymbolAddress((void**)&kl, g_kl);
    cudaGetSymbolAddress((void**)&vh, g_vh); cudaGetSymbolAddress((void**)&vl, g_vl);
    cudaGetSymbolAddress((void**)&wqh,  g_wqkv_hi);
    cudaGetSymbolAddress((void**)&wql,  g_wqkv_lo);
    cudaGetSymbolAddress((void**)&wph,  g_wprj_hi);
    cudaGetSymbolAddress((void**)&wpl,  g_wprj_lo);
    cudaGetSymbolAddress((void**)&w1h,  g_w1_hi);
    cudaGetSymbolAddress((void**)&w1l,  g_w1_lo);
    cudaGetSymbolAddress((void**)&w2h,  g_w2_hi);
    cudaGetSymbolAddress((void**)&w2l,  g_w2_lo);

    cudaFuncSetAttribute(attn_tc_kernel,
        cudaFuncAttributeMaxDynamicSharedMemorySize, ATTN_SMEM);

    // weight splits
    split_kernel<<<(1536 * 512 / 4 + 255) / 256, 256>>>(qkv_w,  wqh, wql, 1536 * 512 / 4);
    split_kernel<<<(512 * 512 / 4 + 255) / 256, 256>>>(proj_w, wph, wpl, 512 * 512 / 4);
    split_kernel<<<(2048 * 512 / 4 + 255) / 256, 256>>>(mlp_w1, w1h, w1l, 2048 * 512 / 4);
    split_kernel<<<(512 * 2048 / 4 + 255) / 256, 256>>>(mlp_w2, w2h, w2l, 512 * 2048 / 4);

    // LN1 -> split
    ln_split_kernel<<<MROWS, 128>>>(x, n1g, n1b, hh_, hl_);
    // QKV (N=1536), emits q/k/v bf16 hi/lo
    mma_gemm<512, EPI_QKV><<<dim3(12, 256), 256>>>(
        hh_, hl_, wqh, wql, nullptr, nullptr, nullptr, nullptr, nullptr,
        qh, ql, kh, kl, vh, vl, 1536);
    // tensor-core attention -> o bf16 hi/lo
    attn_tc_kernel<<<dim3(8, 256), 256, ATTN_SMEM>>>(
        qh, ql, kh, kl, vh, vl, btab, ohh, ohl);
    // proj + residual (N=512)
    mma_gemm<512, EPI_PROJ><<<dim3(4, 256), 256>>>(
        ohh, ohl, wph, wpl, proj_b, x, x1, nullptr, nullptr,
        nullptr, nullptr, nullptr, nullptr, nullptr, nullptr, 512);
    // LN2 -> split
    ln_split_kernel<<<MROWS, 128>>>(x1, n2g, n2b, hh_, hl_);
    // MLP1 + GELU (N=2048)
    mma_gemm<512, EPI_GELU><<<dim3(16, 256), 256>>>(
        hh_, hl_, w1h, w1l, mlp_b1, nullptr, nullptr, hidh, hidl,
        nullptr, nullptr, nullptr, nullptr, nullptr, nullptr, 2048);
    // MLP2 + residual -> out (N=512, K=2048)
    mma_gemm<2048, EPI_OUT><<<dim3(4, 256), 256>>>(
        hidh, hidl, w2h, w2l, mlp_b2, x1, out, nullptr, nullptr,
        nullptr, nullptr, nullptr, nullptr, nullptr, nullptr, 512);
}

// round 6
// speedup vs baseline: 2.5806x; 1.1215x over previous
#include <cuda_runtime.h>
#include <cuda_bf16.h>
#include <math.h>
#include <stdint.h>

// ---------------------------------------------------------------------------
// B=32, N=1024, DIM=512, HEADS=8, HEAD_DIM=64, MLP_HIDDEN=2048. M = 32768.
// GEMMs + attention on mma.sync bf16 (bf16x3 split). cp.async double-buffered
// GEMM mainloop; attention uses ldmatrix.trans for V (no transpose stores).
// ---------------------------------------------------------------------------
#define MROWS 32768
#define DIMC  512
#define HIDC  2048

__device__ float d_x1[MROWS * DIMC];
__device__ __nv_bfloat16 g_h_hi [MROWS * DIMC];
__device__ __nv_bfloat16 g_h_lo [MROWS * DIMC];
__device__ __nv_bfloat16 g_o_hi [MROWS * DIMC];
__device__ __nv_bfloat16 g_o_lo [MROWS * DIMC];
__device__ __nv_bfloat16 g_hid_hi[MROWS * HIDC];
__device__ __nv_bfloat16 g_hid_lo[MROWS * HIDC];
__device__ __nv_bfloat16 g_qh[MROWS * DIMC], g_ql[MROWS * DIMC];
__device__ __nv_bfloat16 g_kh[MROWS * DIMC], g_kl[MROWS * DIMC];
__device__ __nv_bfloat16 g_vh[MROWS * DIMC], g_vl[MROWS * DIMC];
__device__ __nv_bfloat16 g_wqkv_hi[1536 * 512], g_wqkv_lo[1536 * 512];
__device__ __nv_bfloat16 g_wprj_hi[512 * 512],  g_wprj_lo[512 * 512];
__device__ __nv_bfloat16 g_w1_hi [2048 * 512],  g_w1_lo [2048 * 512];
__device__ __nv_bfloat16 g_w2_hi [512 * 2048],  g_w2_lo [512 * 2048];

__device__ __forceinline__ uint32_t smem_u32(const void* p) {
    uint32_t a;
    asm("{ .reg .u64 t; cvta.to.shared.u64 t, %1; cvt.u32.u64 %0, t; }"
        : "=r"(a) : "l"(p));
    return a;
}
__device__ __forceinline__ void ldsm_x4(uint32_t& r0, uint32_t& r1,
                                        uint32_t& r2, uint32_t& r3, uint32_t a) {
    asm volatile("ldmatrix.sync.aligned.m8n8.x4.shared.b16 {%0,%1,%2,%3}, [%4];"
                 : "=r"(r0), "=r"(r1), "=r"(r2), "=r"(r3) : "r"(a));
}
__device__ __forceinline__ void ldsm_x4_t(uint32_t& r0, uint32_t& r1,
                                          uint32_t& r2, uint32_t& r3, uint32_t a) {
    asm volatile("ldmatrix.sync.aligned.m8n8.x4.trans.shared.b16 {%0,%1,%2,%3}, [%4];"
                 : "=r"(r0), "=r"(r1), "=r"(r2), "=r"(r3) : "r"(a));
}
__device__ __forceinline__ void mma_bf16(float* d, const uint32_t* a,
                                         uint32_t b0, uint32_t b1) {
    asm volatile("mma.sync.aligned.m16n8k16.row.col.f32.bf16.bf16.f32 "
                 "{%0,%1,%2,%3}, {%4,%5,%6,%7}, {%8,%9}, {%0,%1,%2,%3};"
                 : "+f"(d[0]), "+f"(d[1]), "+f"(d[2]), "+f"(d[3])
                 : "r"(a[0]), "r"(a[1]), "r"(a[2]), "r"(a[3]), "r"(b0), "r"(b1));
}
__device__ __forceinline__ void cp16(uint32_t s, const void* g) {
    asm volatile("cp.async.cg.shared.global [%0], [%1], 16;" :: "r"(s), "l"(g));
}
__device__ __forceinline__ void pack_hl(float x, float y, uint32_t& hi, uint32_t& lo) {
    __nv_bfloat16 hx = __float2bfloat16(x), hy = __float2bfloat16(y);
    __nv_bfloat162 H; H.x = hx; H.y = hy;
    __nv_bfloat162 L;
    L.x = __float2bfloat16(x - __bfloat162float(hx));
    L.y = __float2bfloat16(y - __bfloat162float(hy));
    hi = *(uint32_t*)&H; lo = *(uint32_t*)&L;
}

// ---------------------------------------------------------------------------
// LayerNorm with fused bf16 hi/lo split output
// ---------------------------------------------------------------------------
__global__ void __launch_bounds__(128) ln_split_kernel(
    const float* __restrict__ x, const float* __restrict__ g,
    const float* __restrict__ b,
    __nv_bfloat16* __restrict__ oh, __nv_bfloat16* __restrict__ ol)
{
    int row = blockIdx.x, t = threadIdx.x;
    float4 vv = reinterpret_cast<const float4*>(x + (size_t)row * DIMC)[t];
    float s  = vv.x + vv.y + vv.z + vv.w;
    float sq = vv.x*vv.x + vv.y*vv.y + vv.z*vv.z + vv.w*vv.w;
    #pragma unroll
    for (int o = 16; o > 0; o >>= 1) {
        s  += __shfl_xor_sync(0xffffffffu, s,  o);
        sq += __shfl_xor_sync(0xffffffffu, sq, o);
    }
    __shared__ float ss[4], sq2[4];
    int w = t >> 5;
    if ((t & 31) == 0) { ss[w] = s; sq2[w] = sq; }
    __syncthreads();
    s  = ss[0] + ss[1] + ss[2] + ss[3];
    sq = sq2[0] + sq2[1] + sq2[2] + sq2[3];
    float mu  = s * (1.f / DIMC);
    float var = sq * (1.f / DIMC) - mu * mu;
    float inv = rsqrtf(var + 1e-5f);
    float4 gv = reinterpret_cast<const float4*>(g)[t];
    float4 bv = reinterpret_cast<const float4*>(b)[t];
    float y0 = (vv.x - mu) * inv * gv.x + bv.x;
    float y1 = (vv.y - mu) * inv * gv.y + bv.y;
    float y2 = (vv.z - mu) * inv * gv.z + bv.z;
    float y3 = (vv.w - mu) * inv * gv.w + bv.w;
    uint32_t h01, l01, h23, l23;
    pack_hl(y0, y1, h01, l01);
    pack_hl(y2, y3, h23, l23);
    uint2 uh; uh.x = h01; uh.y = h23;
    uint2 ul; ul.x = l01; ul.y = l23;
    *(uint2*)(oh + (size_t)row * DIMC + t * 4) = uh;
    *(uint2*)(ol + (size_t)row * DIMC + t * 4) = ul;
}

__global__ void __launch_bounds__(256) split_kernel(
    const float* __restrict__ in, __nv_bfloat16* __restrict__ oh,
    __nv_bfloat16* __restrict__ ol, int n4)
{
    int i = blockIdx.x * 256 + threadIdx.x;
    if (i >= n4) return;
    float4 v = reinterpret_cast<const float4*>(in)[i];
    uint32_t h01, l01, h23, l23;
    pack_hl(v.x, v.y, h01, l01);
    pack_hl(v.z, v.w, h23, l23);
    uint2 uh; uh.x = h01; uh.y = h23;
    uint2 ul; ul.x = l01; ul.y = l23;
    *(uint2*)(oh + (size_t)i * 4) = uh;
    *(uint2*)(ol + (size_t)i * 4) = ul;
}

// ---------------------------------------------------------------------------
// Warp-MMA GEMM, cp.async 2-stage pipeline. CTA 128x128, k-chunk 32.
// Dynamic SMEM: 2 stages x 40960B.
// ---------------------------------------------------------------------------
enum { EPI_QKV = 0, EPI_PROJ = 1, EPI_GELU = 2, EPI_OUT = 3 };

#define LDT 40
#define OFF_AH 0
#define OFF_AL 10240
#define OFF_BH 20480
#define OFF_BL 30720
#define STG    40960
#define GEMM_SMEM (2 * STG)

template<int KTOT, int EPI>
__global__ void __launch_bounds__(256) mma_gemm(
    const __nv_bfloat16* __restrict__ Ah, const __nv_bfloat16* __restrict__ Al,
    const __nv_bfloat16* __restrict__ Bh, const __nv_bfloat16* __restrict__ Bl,
    const float* __restrict__ bias, const float* __restrict__ resid,
    float* __restrict__ out0,
    __nv_bfloat16* __restrict__ obh, __nv_bfloat16* __restrict__ obl,
    __nv_bfloat16* __restrict__ oqh, __nv_bfloat16* __restrict__ oql,
    __nv_bfloat16* __restrict__ okh, __nv_bfloat16* __restrict__ okl,
    __nv_bfloat16* __restrict__ ovh, __nv_bfloat16* __restrict__ ovl, int N)
{
    extern __shared__ __align__(128) char dsm[];
    uint32_t sb = smem_u32(dsm);
    int t = threadIdx.x, wid = t >> 5, lane = t & 31;
    int m0 = blockIdx.y << 7, n0 = blockIdx.x << 7;
    int warp_m = wid & 1, warp_n = wid >> 1;

    float acc[4][4][4];
    #pragma unroll
    for (int i = 0; i < 4; i++)
        #pragma unroll
        for (int j = 0; j < 4; j++)
            #pragma unroll
            for (int r = 0; r < 4; r++) acc[i][j][r] = 0.f;

    int lrow = lane & 15, lcb = (lane >> 4) << 3;
    const int NCH = KTOT / 32;

    // issue cp.async loads for one stage
    auto issue = [&](int stg, int k0) {
        #pragma unroll
        for (int i = t; i < 512; i += 256) {
            int r = i >> 2, q = i & 3;
            size_t ga = (size_t)(m0 + r) * KTOT + k0 + q * 8;
            size_t gb = (size_t)(n0 + r) * KTOT + k0 + q * 8;
            uint32_t off = (uint32_t)stg * STG + (uint32_t)(r * LDT + q * 8) * 2;
            cp16(sb + off + OFF_AH, Ah + ga);
            cp16(sb + off + OFF_AL, Al + ga);
            cp16(sb + off + OFF_BH, Bh + gb);
            cp16(sb + off + OFF_BL, Bl + gb);
        }
        asm volatile("cp.async.commit_group;" ::: "memory");
    };

    issue(0, 0);
    #pragma unroll 1
    for (int ch = 0; ch < NCH; ch++) {
        if (ch + 1 < NCH) {
            issue((ch + 1) & 1, (ch + 1) * 32);
            asm volatile("cp.async.wait_group 1;" ::: "memory");
        } else {
            asm volatile("cp.async.wait_group 0;" ::: "memory");
        }
        __syncthreads();
        uint32_t stb = sb + (uint32_t)(ch & 1) * STG;
        #pragma unroll
        for (int k16 = 0; k16 < 2; k16++) {
            uint32_t afh[4][4], afl[4][4], bfh[2][4], bfl[2][4];
            int col = k16 * 16 + lcb;
            #pragma unroll
            for (int am = 0; am < 4; am++) {
                uint32_t off = (uint32_t)((warp_m * 64 + am * 16 + lrow) * LDT + col) * 2;
                ldsm_x4(afh[am][0], afh[am][1], afh[am][2], afh[am][3], stb + OFF_AH + off);
                ldsm_x4(afl[am][0], afl[am][1], afl[am][2], afl[am][3], stb + OFF_AL + off);
            }
            #pragma unroll
            for (int an2 = 0; an2 < 2; an2++) {
                uint32_t off = (uint32_t)((warp_n * 32 + an2 * 16 + lrow) * LDT + col) * 2;
                ldsm_x4(bfh[an2][0], bfh[an2][1], bfh[an2][2], bfh[an2][3], stb + OFF_BH + off);
                ldsm_x4(bfl[an2][0], bfl[an2][1], bfl[an2][2], bfl[an2][3], stb + OFF_BL + off);
            }
            #pragma unroll
            for (int am = 0; am < 4; am++)
                #pragma unroll
                for (int an = 0; an < 4; an++) {
                    int a2 = an >> 1, p = an & 1;
                    mma_bf16(acc[am][an], afh[am], bfh[a2][p], bfh[a2][p + 2]);
                    mma_bf16(acc[am][an], afh[am], bfl[a2][p], bfl[a2][p + 2]);
                    mma_bf16(acc[am][an], afl[am], bfh[a2][p], bfh[a2][p + 2]);
                }
        }
        __syncthreads();
    }

    float* stage = (float*)dsm;   // [128][68]
    #pragma unroll 1
    for (int hp = 0; hp < 2; hp++) {
        if ((warp_n >> 1) == hp) {
            #pragma unroll
            for (int am = 0; am < 4; am++) {
                int rb = warp_m * 64 + am * 16 + (lane >> 2);
                #pragma unroll
                for (int an = 0; an < 4; an++) {
                    int c = (warp_n & 1) * 32 + an * 8 + (lane & 3) * 2;
                    stage[rb * 68 + c]           = acc[am][an][0];
                    stage[rb * 68 + c + 1]       = acc[am][an][1];
                    stage[(rb + 8) * 68 + c]     = acc[am][an][2];
                    stage[(rb + 8) * 68 + c + 1] = acc[am][an][3];
                }
            }
        }
        __syncthreads();
        for (int i = t; i < 2048; i += 256) {
            int row = i >> 4, c4 = (i & 15) << 2;
            float v0 = stage[row * 68 + c4 + 0];
            float v1 = stage[row * 68 + c4 + 1];
            float v2 = stage[row * 68 + c4 + 2];
            float v3 = stage[row * 68 + c4 + 3];
            int m = m0 + row;
            int n = n0 + hp * 64 + c4;
            if (EPI == EPI_QKV) {
                int sec = n >> 9, hd = (n >> 6) & 7, dd = n & 63;
                int bbq = m >> 10, tok = m & 1023;
                size_t di = (((size_t)bbq * 8 + hd) * 1024 + tok) * 64 + dd;
                __nv_bfloat16 *dh, *dl;
                if (sec == 0)      { dh = oqh; dl = oql; }
                else if (sec == 1) { dh = okh; dl = okl; }
                else               { dh = ovh; dl = ovl; }
                uint32_t h01, l01, h23, l23;
                pack_hl(v0, v1, h01, l01);
                pack_hl(v2, v3, h23, l23);
                uint2 uh; uh.x = h01; uh.y = h23;
                uint2 ul; ul.x = l01; ul.y = l23;
                *(uint2*)(dh + di) = uh;
                *(uint2*)(dl + di) = ul;
            } else if (EPI == EPI_PROJ || EPI == EPI_OUT) {
                float4 rv = *(const float4*)(resid + (size_t)m * N + n);
                float4 bv = *(const float4*)(bias + n);
                float4 ov;
                ov.x = rv.x + v0 + bv.x; ov.y = rv.y + v1 + bv.y;
                ov.z = rv.z + v2 + bv.z; ov.w = rv.w + v3 + bv.w;
                *(float4*)(out0 + (size_t)m * N + n) = ov;
            } else { // EPI_GELU -> bf16 hi/lo split
                float4 bv = *(const float4*)(bias + n);
                float u0 = v0 + bv.x, u1 = v1 + bv.y, u2 = v2 + bv.z, u3 = v3 + bv.w;
                float g0 = 0.5f * u0 * (1.f + erff(u0 * 0.70710678118654752f));
                float g1 = 0.5f * u1 * (1.f + erff(u1 * 0.70710678118654752f));
                float g2 = 0.5f * u2 * (1.f + erff(u2 * 0.70710678118654752f));
                float g3 = 0.5f * u3 * (1.f + erff(u3 * 0.70710678118654752f));
                uint32_t h01, l01, h23, l23;
                pack_hl(g0, g1, h01, l01);
                pack_hl(g2, g3, h23, l23);
                uint2 uh; uh.x = h01; uh.y = h23;
                uint2 ul; ul.x = l01; ul.y = l23;
                *(uint2*)(obh + (size_t)m * HIDC + n) = uh;
                *(uint2*)(obl + (size_t)m * HIDC + n) = ul;
            }
        }
        __syncthreads();
    }
}

// ---------------------------------------------------------------------------
// Tensor-core flash attention; V consumed via ldmatrix.trans (stored [seq][d]).
// ---------------------------------------------------------------------------
#define A_QH 0u
#define A_QL 18432u
#define A_KH 36864u
#define A_KL 46080u
#define A_VH 55296u
#define A_VL 64512u
#define A_BT 73728u
#define A_LI 74752u
#define ATTN_SMEM 75264

__global__ void __launch_bounds__(256) attn_tc_kernel(
    const __nv_bfloat16* __restrict__ qh_g, const __nv_bfloat16* __restrict__ ql_g,
    const __nv_bfloat16* __restrict__ kh_g, const __nv_bfloat16* __restrict__ kl_g,
    const __nv_bfloat16* __restrict__ vh_g, const __nv_bfloat16* __restrict__ vl_g,
    const float* __restrict__ btab_g,
    __nv_bfloat16* __restrict__ ohh, __nv_bfloat16* __restrict__ ohl)
{
    extern __shared__ char sm_[];
    __nv_bfloat16* sqh = (__nv_bfloat16*)(sm_ + A_QH);
    __nv_bfloat16* sql = (__nv_bfloat16*)(sm_ + A_QL);
    __nv_bfloat16* skh = (__nv_bfloat16*)(sm_ + A_KH);
    __nv_bfloat16* skl = (__nv_bfloat16*)(sm_ + A_KL);
    __nv_bfloat16* svh = (__nv_bfloat16*)(sm_ + A_VH);
    __nv_bfloat16* svl = (__nv_bfloat16*)(sm_ + A_VL);
    float* btab = (float*)(sm_ + A_BT);
    float* linv = (float*)(sm_ + A_LI);
    uint32_t sb = smem_u32(sm_);

    int qb = blockIdx.x, bh = blockIdx.y;
    int hh = bh & 7, bb = bh >> 3;
    int t = threadIdx.x, wid = t >> 5, lane = t & 31;
    int lrow = lane & 15, lcb = (lane >> 4) << 3;

    for (int i = t; i < 225; i += 256) btab[i] = btab_g[i * 8 + hh];

    {
        const __nv_bfloat16* qbh = qh_g + ((size_t)bh * 1024 + qb * 128) * 64;
        const __nv_bfloat16* qbl = ql_g + ((size_t)bh * 1024 + qb * 128) * 64;
        for (int i = t; i < 1024; i += 256) {
            int r = i >> 3, c8 = (i & 7) * 8;
            *(uint4*)(sqh + r * 72 + c8) = *(const uint4*)(qbh + r * 64 + c8);
            *(uint4*)(sql + r * 72 + c8) = *(const uint4*)(qbl + r * 64 + c8);
        }
    }
    __syncthreads();
    uint32_t qfh[4][4], qfl[4][4];
    #pragma unroll
    for (int k = 0; k < 4; k++) {
        uint32_t off = (uint32_t)((wid * 16 + lrow) * 72 + k * 16 + lcb) * 2;
        ldsm_x4(qfh[k][0], qfh[k][1], qfh[k][2], qfh[k][3], sb + A_QH + off);
        ldsm_x4(qfl[k][0], qfl[k][1], qfl[k][2], qfl[k][3], sb + A_QL + off);
    }

    float oacc[8][4];
    #pragma unroll
    for (int j = 0; j < 8; j++)
        #pragma unroll
        for (int r = 0; r < 4; r++) oacc[j][r] = 0.f;
    float mrow[2] = {-1e30f, -1e30f}, lsum[2] = {0.f, 0.f};

    int trbase = qb * 128 + wid * 16 + (lane >> 2);

    for (int kt = 0; kt < 16; kt++) {
        const __nv_bfloat16* kbh = kh_g + ((size_t)bh * 1024 + kt * 64) * 64;
        const __nv_bfloat16* kbl = kl_g + ((size_t)bh * 1024 + kt * 64) * 64;
        const __nv_bfloat16* vbh = vh_g + ((size_t)bh * 1024 + kt * 64) * 64;
        const __nv_bfloat16* vbl = vl_g + ((size_t)bh * 1024 + kt * 64) * 64;
        __syncthreads();
        for (int i = t; i < 512; i += 256) {
            int r = i >> 3, c8 = (i & 7) * 8;
            *(uint4*)(skh + r * 72 + c8) = *(const uint4*)(kbh + r * 64 + c8);
            *(uint4*)(skl + r * 72 + c8) = *(const uint4*)(kbl + r * 64 + c8);
            *(uint4*)(svh + r * 72 + c8) = *(const uint4*)(vbh + r * 64 + c8);
            *(uint4*)(svl + r * 72 + c8) = *(const uint4*)(vbl + r * 64 + c8);
        }
        __syncthreads();

        // S = Q K^T
        float sacc[8][4];
        #pragma unroll
        for (int j = 0; j < 8; j++)
            #pragma unroll
            for (int r = 0; r < 4; r++) sacc[j][r] = 0.f;
        #pragma unroll
        for (int k = 0; k < 4; k++) {
            uint32_t bkh[4][4], bkl[4][4];
            #pragma unroll
            for (int g = 0; g < 4; g++) {
                uint32_t off = (uint32_t)((g * 16 + lrow) * 72 + k * 16 + lcb) * 2;
                ldsm_x4(bkh[g][0], bkh[g][1], bkh[g][2], bkh[g][3], sb + A_KH + off);
                ldsm_x4(bkl[g][0], bkl[g][1], bkl[g][2], bkl[g][3], sb + A_KL + off);
            }
            #pragma unroll
            for (int j = 0; j < 8; j++) {
                int g = j >> 1, p = j & 1;
                mma_bf16(sacc[j], qfh[k], bkh[g][p], bkh[g][p + 2]);
                mma_bf16(sacc[j], qfh[k], bkl[g][p], bkl[g][p + 2]);
                mma_bf16(sacc[j], qfl[k], bkh[g][p], bkh[g][p + 2]);
            }
        }

        // bias + online softmax
        #pragma unroll
        for (int h = 0; h < 2; h++) {
            int tr = trbase + h * 8;
            int qy = tr >> 5, qx = tr & 31;
            float m = mrow[h];
            #pragma unroll
            for (int j = 0; j < 8; j++) {
                int tc0 = kt * 64 + j * 8 + (lane & 3) * 2;
                int id0 = (qy - (tc0 >> 5) + 31) * 63 + (qx - (tc0 & 31) + 31);
                id0 = id0 < 224 ? id0 : 224;
                int tc1 = tc0 + 1;
                int id1 = (qy - (tc1 >> 5) + 31) * 63 + (qx - (tc1 & 31) + 31);
                id1 = id1 < 224 ? id1 : 224;
                float s0 = sacc[j][h * 2 + 0] * 0.125f + btab[id0];
                float s1 = sacc[j][h * 2 + 1] * 0.125f + btab[id1];
                sacc[j][h * 2 + 0] = s0; sacc[j][h * 2 + 1] = s1;
                m = fmaxf(m, fmaxf(s0, s1));
            }
            m = fmaxf(m, __shfl_xor_sync(0xffffffffu, m, 1));
            m = fmaxf(m, __shfl_xor_sync(0xffffffffu, m, 2));
            float alpha = __expf(mrow[h] - m);
            float sum = 0.f;
            #pragma unroll
            for (int j = 0; j < 8; j++) {
                float e0 = __expf(sacc[j][h * 2 + 0] - m);
                float e1 = __expf(sacc[j][h * 2 + 1] - m);
                sacc[j][h * 2 + 0] = e0; sacc[j][h * 2 + 1] = e1;
                sum += e0 + e1;
            }
            sum += __shfl_xor_sync(0xffffffffu, sum, 1);
            sum += __shfl_xor_sync(0xffffffffu, sum, 2);
            lsum[h] = lsum[h] * alpha + sum;
            mrow[h] = m;
            #pragma unroll
            for (int j = 0; j < 8; j++) {
                oacc[j][h * 2 + 0] *= alpha;
                oacc[j][h * 2 + 1] *= alpha;
            }
        }

        // pack P into A fragments (hi/lo)
        uint32_t aph[4][4], apl[4][4];
        #pragma unroll
        for (int k = 0; k < 4; k++) {
            int j0 = 2 * k, j1 = 2 * k + 1;
            pack_hl(sacc[j0][0], sacc[j0][1], aph[k][0], apl[k][0]);
            pack_hl(sacc[j0][2], sacc[j0][3], aph[k][1], apl[k][1]);
            pack_hl(sacc[j1][0], sacc[j1][1], aph[k][2], apl[k][2]);
            pack_hl(sacc[j1][2], sacc[j1][3], aph[k][3], apl[k][3]);
        }

        // O += P V : V stored [seq][d]; B-fragments via ldmatrix.trans.
        // tiles: m0=(k0-7,d0-7) m1=(k8-15,d0-7) m2=(k0-7,d8-15) m3=(k8-15,d8-15)
        // d-block half p: b0 = regs[2p], b1 = regs[2p+1]
        #pragma unroll
        for (int k = 0; k < 4; k++) {
            uint32_t bvh[4][4], bvl[4][4];
            #pragma unroll
            for (int g = 0; g < 4; g++) {
                uint32_t off = (uint32_t)((k * 16 + lrow) * 72 + g * 16 + lcb) * 2;
                ldsm_x4_t(bvh[g][0], bvh[g][1], bvh[g][2], bvh[g][3], sb + A_VH + off);
                ldsm_x4_t(bvl[g][0], bvl[g][1], bvl[g][2], bvl[g][3], sb + A_VL + off);
            }
            #pragma unroll
            for (int j = 0; j < 8; j++) {
                int g = j >> 1, p = j & 1;
                mma_bf16(oacc[j], aph[k], bvh[g][p * 2], bvh[g][p * 2 + 1]);
                mma_bf16(oacc[j], aph[k], bvl[g][p * 2], bvl[g][p * 2 + 1]);
                mma_bf16(oacc[j], apl[k], bvh[g][p * 2], bvh[g][p * 2 + 1]);
            }
        }
    }

    // finalize
    if ((lane & 3) == 0) {
        linv[wid * 16 + (lane >> 2)]     = 1.f / lsum[0];
        linv[wid * 16 + (lane >> 2) + 8] = 1.f / lsum[1];
    }
    __syncwarp();
    float* ow = (float*)sm_ + wid * 16 * 66;   // reuse Q region
    #pragma unroll
    for (int j = 0; j < 8; j++) {
        int c = j * 8 + (lane & 3) * 2;
        int r = lane >> 2;
        ow[r * 66 + c]           = oacc[j][0];
        ow[r * 66 + c + 1]       = oacc[j][1];
        ow[(r + 8) * 66 + c]     = oacc[j][2];
        ow[(r + 8) * 66 + c + 1] = oacc[j][3];
    }
    __syncwarp();
    for (int i = lane; i < 256; i += 32) {
        int r = i >> 4, cg = (i & 15) * 4;
        float inv = linv[wid * 16 + r];
        float v0 = ow[r * 66 + cg]     * inv;
        float v1 = ow[r * 66 + cg + 1] * inv;
        float v2 = ow[r * 66 + cg + 2] * inv;
        float v3 = ow[r * 66 + cg + 3] * inv;
        uint32_t h01, l01, h23, l23;
        pack_hl(v0, v1, h01, l01);
        pack_hl(v2, v3, h23, l23);
        size_t go = ((size_t)bb * 1024 + qb * 128 + wid * 16 + r) * 512 + hh * 64 + cg;
        uint2 uh; uh.x = h01; uh.y = h23;
        uint2 ul; ul.x = l01; ul.y = l23;
        *(uint2*)(ohh + go) = uh;
        *(uint2*)(ohl + go) = ul;
    }
}

// ---------------------------------------------------------------------------
// Launcher
// ---------------------------------------------------------------------------
extern "C" void kernel_launch(void* const* d_in, const int* in_sizes, int n_in,
                              void* d_out, int out_size)
{
    const float* x      = (const float*)d_in[0];
    const float* qkv_w  = (const float*)d_in[1];
    const float* proj_w = (const float*)d_in[2];
    const float* proj_b = (const float*)d_in[3];
    const float* mlp_w1 = (const float*)d_in[4];
    const float* mlp_b1 = (const float*)d_in[5];
    const float* mlp_w2 = (const float*)d_in[6];
    const float* mlp_b2 = (const float*)d_in[7];
    const float* n1g    = (const float*)d_in[8];
    const float* n1b    = (const float*)d_in[9];
    const float* n2g    = (const float*)d_in[10];
    const float* n2b    = (const float*)d_in[11];
    const float* btab   = (const float*)d_in[12];
    float* out = (float*)d_out;

    float* x1;
    cudaGetSymbolAddress((void**)&x1, d_x1);
    __nv_bfloat16 *hh_, *hl_, *ohh, *ohl, *hidh, *hidl;
    __nv_bfloat16 *qh, *ql, *kh, *kl, *vh, *vl;
    __nv_bfloat16 *wqh, *wql, *wph, *wpl, *w1h, *w1l, *w2h, *w2l;
    cudaGetSymbolAddress((void**)&hh_,  g_h_hi);
    cudaGetSymbolAddress((void**)&hl_,  g_h_lo);
    cudaGetSymbolAddress((void**)&ohh,  g_o_hi);
    cudaGetSymbolAddress((void**)&ohl,  g_o_lo);
    cudaGetSymbolAddress((void**)&hidh, g_hid_hi);
    cudaGetSymbolAddress((void**)&hidl, g_hid_lo);
    cudaGetSymbolAddress((void**)&qh, g_qh); cudaGetSymbolAddress((void**)&ql, g_ql);
    cudaGetSymbolAddress((void**)&kh, g_kh); cudaGetSymbolAddress((void**)&kl, g_kl);
    cudaGetSymbolAddress((void**)&vh, g_vh); cudaGetSymbolAddress((void**)&vl, g_vl);
    cudaGetSymbolAddress((void**)&wqh,  g_wqkv_hi);
    cudaGetSymbolAddress((void**)&wql,  g_wqkv_lo);
    cudaGetSymbolAddress((void**)&wph,  g_wprj_hi);
    cudaGetSymbolAddress((void**)&wpl,  g_wprj_lo);
    cudaGetSymbolAddress((void**)&w1h,  g_w1_hi);
    cudaGetSymbolAddress((void**)&w1l,  g_w1_lo);
    cudaGetSymbolAddress((void**)&w2h,  g_w2_hi);
    cudaGetSymbolAddress((void**)&w2l,  g_w2_lo);

    cudaFuncSetAttribute(attn_tc_kernel,
        cudaFuncAttributeMaxDynamicSharedMemorySize, ATTN_SMEM);
    cudaFuncSetAttribute(mma_gemm<512, EPI_QKV>,
        cudaFuncAttributeMaxDynamicSharedMemorySize, GEMM_SMEM);
    cudaFuncSetAttribute(mma_gemm<512, EPI_PROJ>,
        cudaFuncAttributeMaxDynamicSharedMemorySize, GEMM_SMEM);
    cudaFuncSetAttribute(mma_gemm<512, EPI_GELU>,
        cudaFuncAttributeMaxDynamicSharedMemorySize, GEMM_SMEM);
    cudaFuncSetAttribute(mma_gemm<2048, EPI_OUT>,
        cudaFuncAttributeMaxDynamicSharedMemorySize, GEMM_SMEM);

    // weight splits
    split_kernel<<<(1536 * 512 / 4 + 255) / 256, 256>>>(qkv_w,  wqh, wql, 1536 * 512 / 4);
    split_kernel<<<(512 * 512 / 4 + 255) / 256, 256>>>(proj_w, wph, wpl, 512 * 512 / 4);
    split_kernel<<<(2048 * 512 / 4 + 255) / 256, 256>>>(mlp_w1, w1h, w1l, 2048 * 512 / 4);
    split_kernel<<<(512 * 2048 / 4 + 255) / 256, 256>>>(mlp_w2, w2h, w2l, 512 * 2048 / 4);

    // LN1 -> split
    ln_split_kernel<<<MROWS, 128>>>(x, n1g, n1b, hh_, hl_);
    // QKV (N=1536)
    mma_gemm<512, EPI_QKV><<<dim3(12, 256), 256, GEMM_SMEM>>>(
        hh_, hl_, wqh, wql, nullptr, nullptr, nullptr, nullptr, nullptr,
        qh, ql, kh, kl, vh, vl, 1536);
    // attention
    attn_tc_kernel<<<dim3(8, 256), 256, ATTN_SMEM>>>(
        qh, ql, kh, kl, vh, vl, btab, ohh, ohl);
    // proj + residual (N=512)
    mma_gemm<512, EPI_PROJ><<<dim3(4, 256), 256, GEMM_SMEM>>>(
        ohh, ohl, wph, wpl, proj_b, x, x1, nullptr, nullptr,
        nullptr, nullptr, nullptr, nullptr, nullptr, nullptr, 512);
    // LN2 -> split
    ln_split_kernel<<<MROWS, 128>>>(x1, n2g, n2b, hh_, hl_);
    // MLP1 + GELU (N=2048)
    mma_gemm<512, EPI_GELU><<<dim3(16, 256), 256, GEMM_SMEM>>>(
        hh_, hl_, w1h, w1l, mlp_b1, nullptr, nullptr, hidh, hidl,
        nullptr, nullptr, nullptr, nullptr, nullptr, nullptr, 2048);
    // MLP2 + residual -> out (N=512, K=2048)
    mma_gemm<2048, EPI_OUT><<<dim3(4, 256), 256, GEMM_SMEM>>>(
        hidh, hidl, w2h, w2l, mlp_b2, x1, out, nullptr, nullptr,
        nullptr, nullptr, nullptr, nullptr, nullptr, nullptr, 512);
}

// round 7
// speedup vs baseline: 6.4446x; 2.4974x over previous
#include <cuda_runtime.h>
#include <cuda_fp16.h>
#include <math.h>
#include <stdint.h>

// ---------------------------------------------------------------------------
// B=32, N=1024, DIM=512, HEADS=8, HEAD_DIM=64, MLP_HIDDEN=2048. M = 32768.
// GEMMs + attention on mma.sync fp16 (single precision-level: err ~2^-12,
// measured total ~1e-4 << 1e-3). 3-stage cp.async pipelines everywhere.
// ---------------------------------------------------------------------------
#define MROWS 32768
#define DIMC  512
#define HIDC  2048

__device__ float d_x1[MROWS * DIMC];
__device__ __half g_h  [MROWS * DIMC];
__device__ __half g_o  [MROWS * DIMC];
__device__ __half g_hid[MROWS * HIDC];
__device__ __half g_q  [MROWS * DIMC];
__device__ __half g_k  [MROWS * DIMC];
__device__ __half g_v  [MROWS * DIMC];
__device__ __half g_wqkv[1536 * 512];
__device__ __half g_wprj[512 * 512];
__device__ __half g_w1 [2048 * 512];
__device__ __half g_w2 [512 * 2048];

__device__ __forceinline__ uint32_t smem_u32(const void* p) {
    uint32_t a;
    asm("{ .reg .u64 t; cvta.to.shared.u64 t, %1; cvt.u32.u64 %0, t; }"
        : "=r"(a) : "l"(p));
    return a;
}
__device__ __forceinline__ void ldsm_x4(uint32_t& r0, uint32_t& r1,
                                        uint32_t& r2, uint32_t& r3, uint32_t a) {
    asm volatile("ldmatrix.sync.aligned.m8n8.x4.shared.b16 {%0,%1,%2,%3}, [%4];"
                 : "=r"(r0), "=r"(r1), "=r"(r2), "=r"(r3) : "r"(a));
}
__device__ __forceinline__ void ldsm_x4_t(uint32_t& r0, uint32_t& r1,
                                          uint32_t& r2, uint32_t& r3, uint32_t a) {
    asm volatile("ldmatrix.sync.aligned.m8n8.x4.trans.shared.b16 {%0,%1,%2,%3}, [%4];"
                 : "=r"(r0), "=r"(r1), "=r"(r2), "=r"(r3) : "r"(a));
}
__device__ __forceinline__ void mma_f16(float* d, const uint32_t* a,
                                        uint32_t b0, uint32_t b1) {
    asm volatile("mma.sync.aligned.m16n8k16.row.col.f32.f16.f16.f32 "
                 "{%0,%1,%2,%3}, {%4,%5,%6,%7}, {%8,%9}, {%0,%1,%2,%3};"
                 : "+f"(d[0]), "+f"(d[1]), "+f"(d[2]), "+f"(d[3])
                 : "r"(a[0]), "r"(a[1]), "r"(a[2]), "r"(a[3]), "r"(b0), "r"(b1));
}
__device__ __forceinline__ void cp16(uint32_t s, const void* g) {
    asm volatile("cp.async.cg.shared.global [%0], [%1], 16;" :: "r"(s), "l"(g));
}
__device__ __forceinline__ uint32_t pack2h(float x, float y) {
    __half2 h = __floats2half2_rn(x, y);
    return *(uint32_t*)&h;
}

// ---------------------------------------------------------------------------
// LayerNorm -> fp16
// ---------------------------------------------------------------------------
__global__ void __launch_bounds__(128) ln_h_kernel(
    const float* __restrict__ x, const float* __restrict__ g,
    const float* __restrict__ b, __half* __restrict__ oh)
{
    int row = blockIdx.x, t = threadIdx.x;
    float4 vv = reinterpret_cast<const float4*>(x + (size_t)row * DIMC)[t];
    float s  = vv.x + vv.y + vv.z + vv.w;
    float sq = vv.x*vv.x + vv.y*vv.y + vv.z*vv.z + vv.w*vv.w;
    #pragma unroll
    for (int o = 16; o > 0; o >>= 1) {
        s  += __shfl_xor_sync(0xffffffffu, s,  o);
        sq += __shfl_xor_sync(0xffffffffu, sq, o);
    }
    __shared__ float ss[4], sq2[4];
    int w = t >> 5;
    if ((t & 31) == 0) { ss[w] = s; sq2[w] = sq; }
    __syncthreads();
    s  = ss[0] + ss[1] + ss[2] + ss[3];
    sq = sq2[0] + sq2[1] + sq2[2] + sq2[3];
    float mu  = s * (1.f / DIMC);
    float var = sq * (1.f / DIMC) - mu * mu;
    float inv = rsqrtf(var + 1e-5f);
    float4 gv = reinterpret_cast<const float4*>(g)[t];
    float4 bv = reinterpret_cast<const float4*>(b)[t];
    uint2 u;
    u.x = pack2h((vv.x - mu) * inv * gv.x + bv.x, (vv.y - mu) * inv * gv.y + bv.y);
    u.y = pack2h((vv.z - mu) * inv * gv.z + bv.z, (vv.w - mu) * inv * gv.w + bv.w);
    *(uint2*)(oh + (size_t)row * DIMC + t * 4) = u;
}

// fp32 -> fp16 convert (weights)
__global__ void __launch_bounds__(256) cvt_kernel(
    const float* __restrict__ in, __half* __restrict__ oh, int n4)
{
    int i = blockIdx.x * 256 + threadIdx.x;
    if (i >= n4) return;
    float4 v = reinterpret_cast<const float4*>(in)[i];
    uint2 u;
    u.x = pack2h(v.x, v.y);
    u.y = pack2h(v.z, v.w);
    *(uint2*)(oh + (size_t)i * 4) = u;
}

// ---------------------------------------------------------------------------
// Warp-MMA fp16 GEMM, 3-stage cp.async pipeline. CTA 128x128, k-chunk 32.
// ---------------------------------------------------------------------------
enum { EPI_QKV = 0, EPI_PROJ = 1, EPI_GELU = 2, EPI_OUT = 3 };

#define LDT 40
#define OFF_A 0
#define OFF_B 10240
#define STG   20480
#define GEMM_SMEM (3 * STG)

template<int KTOT, int EPI>
__global__ void __launch_bounds__(256) mma_gemm(
    const __half* __restrict__ A, const __half* __restrict__ B,
    const float* __restrict__ bias, const float* __restrict__ resid,
    float* __restrict__ out0, __half* __restrict__ oh,
    __half* __restrict__ oq, __half* __restrict__ ok,
    __half* __restrict__ ov, int N)
{
    extern __shared__ __align__(128) char dsm[];
    uint32_t sb = smem_u32(dsm);
    int t = threadIdx.x, wid = t >> 5, lane = t & 31;
    int m0 = blockIdx.y << 7, n0 = blockIdx.x << 7;
    int warp_m = wid & 1, warp_n = wid >> 1;

    float acc[4][4][4];
    #pragma unroll
    for (int i = 0; i < 4; i++)
        #pragma unroll
        for (int j = 0; j < 4; j++)
            #pragma unroll
            for (int r = 0; r < 4; r++) acc[i][j][r] = 0.f;

    int lrow = lane & 15, lcb = (lane >> 4) << 3;
    const int NCH = KTOT / 32;

    auto issue = [&](int stg, int k0) {
        #pragma unroll
        for (int i = t; i < 512; i += 256) {
            int r = i >> 2, q = i & 3;
            size_t ga = (size_t)(m0 + r) * KTOT + k0 + q * 8;
            size_t gb = (size_t)(n0 + r) * KTOT + k0 + q * 8;
            uint32_t off = (uint32_t)stg * STG + (uint32_t)(r * LDT + q * 8) * 2;
            cp16(sb + off + OFF_A, A + ga);
            cp16(sb + off + OFF_B, B + gb);
        }
        asm volatile("cp.async.commit_group;" ::: "memory");
    };

    issue(0, 0);
    if (NCH > 1) issue(1, 32);
    #pragma unroll 1
    for (int ch = 0; ch < NCH; ch++) {
        if (ch + 1 < NCH)
            asm volatile("cp.async.wait_group 1;" ::: "memory");
        else
            asm volatile("cp.async.wait_group 0;" ::: "memory");
        __syncthreads();
        uint32_t stb = sb + (uint32_t)(ch % 3) * STG;
        #pragma unroll
        for (int k16 = 0; k16 < 2; k16++) {
            uint32_t af[4][4], bf[2][4];
            int col = k16 * 16 + lcb;
            #pragma unroll
            for (int am = 0; am < 4; am++) {
                uint32_t off = (uint32_t)((warp_m * 64 + am * 16 + lrow) * LDT + col) * 2;
                ldsm_x4(af[am][0], af[am][1], af[am][2], af[am][3], stb + OFF_A + off);
            }
            #pragma unroll
            for (int an2 = 0; an2 < 2; an2++) {
                uint32_t off = (uint32_t)((warp_n * 32 + an2 * 16 + lrow) * LDT + col) * 2;
                ldsm_x4(bf[an2][0], bf[an2][1], bf[an2][2], bf[an2][3], stb + OFF_B + off);
            }
            #pragma unroll
            for (int am = 0; am < 4; am++)
                #pragma unroll
                for (int an = 0; an < 4; an++) {
                    int a2 = an >> 1, p = an & 1;
                    mma_f16(acc[am][an], af[am], bf[a2][p], bf[a2][p + 2]);
                }
        }
        if (ch + 2 < NCH) issue((ch + 2) % 3, (ch + 2) * 32);
    }
    __syncthreads();

    float* stage = (float*)dsm;   // [128][68]
    #pragma unroll 1
    for (int hp = 0; hp < 2; hp++) {
        if ((warp_n >> 1) == hp) {
            #pragma unroll
            for (int am = 0; am < 4; am++) {
                int rb = warp_m * 64 + am * 16 + (lane >> 2);
                #pragma unroll
                for (int an = 0; an < 4; an++) {
                    int c = (warp_n & 1) * 32 + an * 8 + (lane & 3) * 2;
                    stage[rb * 68 + c]           = acc[am][an][0];
                    stage[rb * 68 + c + 1]       = acc[am][an][1];
                    stage[(rb + 8) * 68 + c]     = acc[am][an][2];
                    stage[(rb + 8) * 68 + c + 1] = acc[am][an][3];
                }
            }
        }
        __syncthreads();
        for (int i = t; i < 2048; i += 256) {
            int row = i >> 4, c4 = (i & 15) << 2;
            float v0 = stage[row * 68 + c4 + 0];
            float v1 = stage[row * 68 + c4 + 1];
            float v2 = stage[row * 68 + c4 + 2];
            float v3 = stage[row * 68 + c4 + 3];
            int m = m0 + row;
            int n = n0 + hp * 64 + c4;
            if (EPI == EPI_QKV) {
                int sec = n >> 9, hd = (n >> 6) & 7, dd = n & 63;
                int bbq = m >> 10, tok = m & 1023;
                size_t di = (((size_t)bbq * 8 + hd) * 1024 + tok) * 64 + dd;
                __half* dst = (sec == 0) ? oq : ((sec == 1) ? ok : ov);
                uint2 u;
                u.x = pack2h(v0, v1);
                u.y = pack2h(v2, v3);
                *(uint2*)(dst + di) = u;
            } else if (EPI == EPI_PROJ || EPI == EPI_OUT) {
                float4 rv = *(const float4*)(resid + (size_t)m * N + n);
                float4 bv = *(const float4*)(bias + n);
                float4 ovv;
                ovv.x = rv.x + v0 + bv.x; ovv.y = rv.y + v1 + bv.y;
                ovv.z = rv.z + v2 + bv.z; ovv.w = rv.w + v3 + bv.w;
                *(float4*)(out0 + (size_t)m * N + n) = ovv;
            } else { // EPI_GELU -> fp16
                float4 bv = *(const float4*)(bias + n);
                float u0 = v0 + bv.x, u1 = v1 + bv.y, u2 = v2 + bv.z, u3 = v3 + bv.w;
                float g0 = 0.5f * u0 * (1.f + erff(u0 * 0.70710678118654752f));
                float g1 = 0.5f * u1 * (1.f + erff(u1 * 0.70710678118654752f));
                float g2 = 0.5f * u2 * (1.f + erff(u2 * 0.70710678118654752f));
                float g3 = 0.5f * u3 * (1.f + erff(u3 * 0.70710678118654752f));
                uint2 u;
                u.x = pack2h(g0, g1);
                u.y = pack2h(g2, g3);
                *(uint2*)(oh + (size_t)m * HIDC + n) = u;
            }
        }
        __syncthreads();
    }
}

// ---------------------------------------------------------------------------
// fp16 tensor-core flash attention, 3-stage cp.async K/V pipeline.
// SMEM: Q [128][72] @0 (18432B); KV stages s=0..2 @18432+s*18432
//       (K 64x72 = 9216B, V 64x72 = 9216B); btab @73728; linv @74752.
// ---------------------------------------------------------------------------
#define A_Q  0u
#define A_KV 18432u
#define KV_STG 18432u
#define A_BT 73728u
#define A_LI 74752u
#define ATTN_SMEM 75264

__global__ void __launch_bounds__(256) attn_tc_kernel(
    const __half* __restrict__ q_g, const __half* __restrict__ k_g,
    const __half* __restrict__ v_g, const float* __restrict__ btab_g,
    __half* __restrict__ o_g)
{
    extern __shared__ char sm_[];
    __half* sq = (__half*)(sm_ + A_Q);
    float* btab = (float*)(sm_ + A_BT);
    float* linv = (float*)(sm_ + A_LI);
    uint32_t sb = smem_u32(sm_);

    int qb = blockIdx.x, bh = blockIdx.y;
    int hh = bh & 7, bb = bh >> 3;
    int t = threadIdx.x, wid = t >> 5, lane = t & 31;
    int lrow = lane & 15, lcb = (lane >> 4) << 3;

    const __half* kb = k_g + (size_t)bh * 1024 * 64;
    const __half* vb = v_g + (size_t)bh * 1024 * 64;

    auto issueKV = [&](int kt) {
        uint32_t base = sb + A_KV + (uint32_t)(kt % 3) * KV_STG;
        const __half* kp = kb + (size_t)kt * 64 * 64;
        const __half* vp = vb + (size_t)kt * 64 * 64;
        #pragma unroll
        for (int i = t; i < 512; i += 256) {
            int r = i >> 3, c8 = (i & 7) * 8;
            uint32_t off = (uint32_t)(r * 72 + c8) * 2;
            cp16(base + off, kp + r * 64 + c8);
            cp16(base + 9216 + off, vp + r * 64 + c8);
        }
        asm volatile("cp.async.commit_group;" ::: "memory");
    };

    for (int i = t; i < 225; i += 256) btab[i] = btab_g[i * 8 + hh];
    {
        const __half* qg = q_g + ((size_t)bh * 1024 + qb * 128) * 64;
        for (int i = t; i < 1024; i += 256) {
            int r = i >> 3, c8 = (i & 7) * 8;
            *(uint4*)(sq + r * 72 + c8) = *(const uint4*)(qg + r * 64 + c8);
        }
    }
    issueKV(0);
    issueKV(1);
    __syncthreads();
    uint32_t qf[4][4];
    #pragma unroll
    for (int k = 0; k < 4; k++) {
        uint32_t off = (uint32_t)((wid * 16 + lrow) * 72 + k * 16 + lcb) * 2;
        ldsm_x4(qf[k][0], qf[k][1], qf[k][2], qf[k][3], sb + A_Q + off);
    }

    float oacc[8][4];
    #pragma unroll
    for (int j = 0; j < 8; j++)
        #pragma unroll
        for (int r = 0; r < 4; r++) oacc[j][r] = 0.f;
    float mrow[2] = {-1e30f, -1e30f}, lsum[2] = {0.f, 0.f};
    int trbase = qb * 128 + wid * 16 + (lane >> 2);

    #pragma unroll 1
    for (int kt = 0; kt < 16; kt++) {
        if (kt < 15)
            asm volatile("cp.async.wait_group 1;" ::: "memory");
        else
            asm volatile("cp.async.wait_group 0;" ::: "memory");
        __syncthreads();
        uint32_t kbase = sb + A_KV + (uint32_t)(kt % 3) * KV_STG;
        uint32_t vbase = kbase + 9216;

        // S = Q K^T
        float sacc[8][4];
        #pragma unroll
        for (int j = 0; j < 8; j++)
            #pragma unroll
            for (int r = 0; r < 4; r++) sacc[j][r] = 0.f;
        #pragma unroll
        for (int k = 0; k < 4; k++) {
            uint32_t bk[4][4];
            #pragma unroll
            for (int g = 0; g < 4; g++) {
                uint32_t off = (uint32_t)((g * 16 + lrow) * 72 + k * 16 + lcb) * 2;
                ldsm_x4(bk[g][0], bk[g][1], bk[g][2], bk[g][3], kbase + off);
            }
            #pragma unroll
            for (int j = 0; j < 8; j++) {
                int g = j >> 1, p = j & 1;
                mma_f16(sacc[j], qf[k], bk[g][p], bk[g][p + 2]);
            }
        }

        // bias + online softmax
        #pragma unroll
        for (int h = 0; h < 2; h++) {
            int tr = trbase + h * 8;
            int qy = tr >> 5, qx = tr & 31;
            float m = mrow[h];
            #pragma unroll
            for (int j = 0; j < 8; j++) {
                int tc0 = kt * 64 + j * 8 + (lane & 3) * 2;
                int id0 = (qy - (tc0 >> 5) + 31) * 63 + (qx - (tc0 & 31) + 31);
                id0 = id0 < 224 ? id0 : 224;
                int tc1 = tc0 + 1;
                int id1 = (qy - (tc1 >> 5) + 31) * 63 + (qx - (tc1 & 31) + 31);
                id1 = id1 < 224 ? id1 : 224;
                float s0 = sacc[j][h * 2 + 0] * 0.125f + btab[id0];
                float s1 = sacc[j][h * 2 + 1] * 0.125f + btab[id1];
                sacc[j][h * 2 + 0] = s0; sacc[j][h * 2 + 1] = s1;
                m = fmaxf(m, fmaxf(s0, s1));
            }
            m = fmaxf(m, __shfl_xor_sync(0xffffffffu, m, 1));
            m = fmaxf(m, __shfl_xor_sync(0xffffffffu, m, 2));
            float alpha = __expf(mrow[h] - m);
            float sum = 0.f;
            #pragma unroll
            for (int j = 0; j < 8; j++) {
                float e0 = __expf(sacc[j][h * 2 + 0] - m);
                float e1 = __expf(sacc[j][h * 2 + 1] - m);
                sacc[j][h * 2 + 0] = e0; sacc[j][h * 2 + 1] = e1;
                sum += e0 + e1;
            }
            sum += __shfl_xor_sync(0xffffffffu, sum, 1);
            sum += __shfl_xor_sync(0xffffffffu, sum, 2);
            lsum[h] = lsum[h] * alpha + sum;
            mrow[h] = m;
            #pragma unroll
            for (int j = 0; j < 8; j++) {
                oacc[j][h * 2 + 0] *= alpha;
                oacc[j][h * 2 + 1] *= alpha;
            }
        }

        // P -> fp16 A fragments
        uint32_t ap[4][4];
        #pragma unroll
        for (int k = 0; k < 4; k++) {
            int j0 = 2 * k, j1 = 2 * k + 1;
            ap[k][0] = pack2h(sacc[j0][0], sacc[j0][1]);
            ap[k][1] = pack2h(sacc[j0][2], sacc[j0][3]);
            ap[k][2] = pack2h(sacc[j1][0], sacc[j1][1]);
            ap[k][3] = pack2h(sacc[j1][2], sacc[j1][3]);
        }

        // O += P V, V [seq][d] via ldmatrix.trans
        #pragma unroll
        for (int k = 0; k < 4; k++) {
            uint32_t bv[4][4];
            #pragma unroll
            for (int g = 0; g < 4; g++) {
                uint32_t off = (uint32_t)((k * 16 + lrow) * 72 + g * 16 + lcb) * 2;
                ldsm_x4_t(bv[g][0], bv[g][1], bv[g][2], bv[g][3], vbase + off);
            }
            #pragma unroll
            for (int j = 0; j < 8; j++) {
                int g = j >> 1, p = j & 1;
                mma_f16(oacc[j], ap[k], bv[g][p * 2], bv[g][p * 2 + 1]);
            }
        }
        if (kt + 2 < 16) issueKV(kt + 2);
    }

    // finalize
    if ((lane & 3) == 0) {
        linv[wid * 16 + (lane >> 2)]     = 1.f / lsum[0];
        linv[wid * 16 + (lane >> 2) + 8] = 1.f / lsum[1];
    }
    __syncthreads();
    float* ow = (float*)sm_ + wid * 16 * 66;
    #pragma unroll
    for (int j = 0; j < 8; j++) {
        int c = j * 8 + (lane & 3) * 2;
        int r = lane >> 2;
        ow[r * 66 + c]           = oacc[j][0];
        ow[r * 66 + c + 1]       = oacc[j][1];
        ow[(r + 8) * 66 + c]     = oacc[j][2];
        ow[(r + 8) * 66 + c + 1] = oacc[j][3];
    }
    __syncwarp();
    for (int i = lane; i < 256; i += 32) {
        int r = i >> 4, cg = (i & 15) * 4;
        float inv = linv[wid * 16 + r];
        uint2 u;
        u.x = pack2h(ow[r * 66 + cg] * inv,     ow[r * 66 + cg + 1] * inv);
        u.y = pack2h(ow[r * 66 + cg + 2] * inv, ow[r * 66 + cg + 3] * inv);
        size_t go = ((size_t)bb * 1024 + qb * 128 + wid * 16 + r) * 512 + hh * 64 + cg;
        *(uint2*)(o_g + go) = u;
    }
}

// ---------------------------------------------------------------------------
// Launcher
// ---------------------------------------------------------------------------
extern "C" void kernel_launch(void* const* d_in, const int* in_sizes, int n_in,
                              void* d_out, int out_size)
{
    const float* x      = (const float*)d_in[0];
    const float* qkv_w  = (const float*)d_in[1];
    const float* proj_w = (const float*)d_in[2];
    const float* proj_b = (const float*)d_in[3];
    const float* mlp_w1 = (const float*)d_in[4];
    const float* mlp_b1 = (const float*)d_in[5];
    const float* mlp_w2 = (const float*)d_in[6];
    const float* mlp_b2 = (const float*)d_in[7];
    const float* n1g    = (const float*)d_in[8];
    const float* n1b    = (const float*)d_in[9];
    const float* n2g    = (const float*)d_in[10];
    const float* n2b    = (const float*)d_in[11];
    const float* btab   = (const float*)d_in[12];
    float* out = (float*)d_out;

    float* x1;
    cudaGetSymbolAddress((void**)&x1, d_x1);
    __half *h_, *o_, *hid, *q, *k, *v, *wq, *wp, *w1, *w2;
    cudaGetSymbolAddress((void**)&h_,  g_h);
    cudaGetSymbolAddress((void**)&o_,  g_o);
    cudaGetSymbolAddress((void**)&hid, g_hid);
    cudaGetSymbolAddress((void**)&q,   g_q);
    cudaGetSymbolAddress((void**)&k,   g_k);
    cudaGetSymbolAddress((void**)&v,   g_v);
    cudaGetSymbolAddress((void**)&wq,  g_wqkv);
    cudaGetSymbolAddress((void**)&wp,  g_wprj);
    cudaGetSymbolAddress((void**)&w1,  g_w1);
    cudaGetSymbolAddress((void**)&w2,  g_w2);

    cudaFuncSetAttribute(attn_tc_kernel,
        cudaFuncAttributeMaxDynamicSharedMemorySize, ATTN_SMEM);
    cudaFuncSetAttribute(mma_gemm<512, EPI_QKV>,
        cudaFuncAttributeMaxDynamicSharedMemorySize, GEMM_SMEM);
    cudaFuncSetAttribute(mma_gemm<512, EPI_PROJ>,
        cudaFuncAttributeMaxDynamicSharedMemorySize, GEMM_SMEM);
    cudaFuncSetAttribute(mma_gemm<512, EPI_GELU>,
        cudaFuncAttributeMaxDynamicSharedMemorySize, GEMM_SMEM);
    cudaFuncSetAttribute(mma_gemm<2048, EPI_OUT>,
        cudaFuncAttributeMaxDynamicSharedMemorySize, GEMM_SMEM);

    // weight converts
    cvt_kernel<<<(1536 * 512 / 4 + 255) / 256, 256>>>(qkv_w,  wq, 1536 * 512 / 4);
    cvt_kernel<<<(512 * 512 / 4 + 255) / 256, 256>>>(proj_w, wp, 512 * 512 / 4);
    cvt_kernel<<<(2048 * 512 / 4 + 255) / 256, 256>>>(mlp_w1, w1, 2048 * 512 / 4);
    cvt_kernel<<<(512 * 2048 / 4 + 255) / 256, 256>>>(mlp_w2, w2, 512 * 2048 / 4);

    // LN1
    ln_h_kernel<<<MROWS, 128>>>(x, n1g, n1b, h_);
    // QKV (N=1536)
    mma_gemm<512, EPI_QKV><<<dim3(12, 256), 256, GEMM_SMEM>>>(
        h_, wq, nullptr, nullptr, nullptr, nullptr, q, k, v, 1536);
    // attention
    attn_tc_kernel<<<dim3(8, 256), 256, ATTN_SMEM>>>(q, k, v, btab, o_);
    // proj + residual (N=512)
    mma_gemm<512, EPI_PROJ><<<dim3(4, 256), 256, GEMM_SMEM>>>(
        o_, wp, proj_b, x, x1, nullptr, nullptr, nullptr, nullptr, 512);
    // LN2
    ln_h_kernel<<<MROWS, 128>>>(x1, n2g, n2b, h_);
    // MLP1 + GELU (N=2048)
    mma_gemm<512, EPI_GELU><<<dim3(16, 256), 256, GEMM_SMEM>>>(
        h_, w1, mlp_b1, nullptr, nullptr, hid, nullptr, nullptr, nullptr, 2048);
    // MLP2 + residual -> out (N=512, K=2048)
    mma_gemm<2048, EPI_OUT><<<dim3(4, 256), 256, GEMM_SMEM>>>(
        hid, w2, mlp_b2, x1, out, nullptr, nullptr, nullptr, nullptr, 512);
}